// round 13
// baseline (speedup 1.0000x reference)
#include <cuda_runtime.h>
#include <cuda_bf16.h>
#include <cuda_fp8.h>
#include <stdint.h>

#define BB  2
#define SS  2048
#define DIM 1024
#define HH  16
#define DD  64
#define MT  (BB*SS)
#define NBH (BB*HH)

// ---- device scratch ----
__device__ __nv_bfloat16 g_xh[3][MT*DIM];
__device__ uint8_t       g_x8h[3][MT*DIM], g_x8l[3][MT*DIM];
__device__ __nv_bfloat16 g_twh[4][DIM*DIM];
__device__ uint8_t       g_tw8h[4][DIM*DIM], g_tw8l[4][DIM*DIM];
__device__ __nv_bfloat16 g_ph[3][NBH*SS*DD];
__device__ uint8_t       g_p8h[3][NBH*SS*DD], g_p8l[3][NBH*SS*DD];
__device__ __nv_bfloat16 g_vth[NBH*DD*SS];
__device__ uint8_t       g_vt8h[NBH*DD*SS], g_vt8l[NBH*DD*SS];
__device__ __nv_bfloat16 g_ch[MT*DIM];
__device__ uint8_t       g_c8h[MT*DIM], g_c8l[MT*DIM];
__device__ float2 g_part[(size_t)NBH*SS*16];
__device__ float2 g_ms[(size_t)NBH*SS];

// ---- helpers ----
__device__ __forceinline__ uint32_t s2u(const void* p){
    uint32_t a;
    asm("{ .reg .u64 t; cvta.to.shared.u64 t, %1; cvt.u32.u64 %0, t; }":"=r"(a):"l"(p));
    return a;
}
__device__ __forceinline__ uint8_t f2e4(float v){
    return (uint8_t)__nv_cvt_float_to_fp8(v, __NV_SATFINITE, __NV_E4M3);
}
__device__ __forceinline__ uint32_t pk8x4(uint8_t a, uint8_t b, uint8_t c, uint8_t d){
    return (uint32_t)a | ((uint32_t)b<<8) | ((uint32_t)c<<16) | ((uint32_t)d<<24);
}
__device__ __forceinline__ uint32_t pk2(__nv_bfloat16 a, __nv_bfloat16 b){
    __nv_bfloat162 t(a, b); return *(uint32_t*)&t;
}
__device__ __forceinline__ void ldmx4(uint32_t* r, uint32_t addr){
    asm volatile("ldmatrix.sync.aligned.m8n8.x4.shared.b16 {%0,%1,%2,%3}, [%4];"
        : "=r"(r[0]),"=r"(r[1]),"=r"(r[2]),"=r"(r[3]) : "r"(addr));
}
__device__ __forceinline__ void ldmx2(uint32_t* r, uint32_t addr){
    asm volatile("ldmatrix.sync.aligned.m8n8.x2.shared.b16 {%0,%1}, [%2];"
        : "=r"(r[0]),"=r"(r[1]) : "r"(addr));
}
__device__ __forceinline__ void mma16816(float* c, const uint32_t* a, const uint32_t* b){
    asm volatile("mma.sync.aligned.m16n8k16.row.col.f32.bf16.bf16.f32 "
        "{%0,%1,%2,%3}, {%4,%5,%6,%7}, {%8,%9}, {%0,%1,%2,%3};"
        : "+f"(c[0]),"+f"(c[1]),"+f"(c[2]),"+f"(c[3])
        : "r"(a[0]),"r"(a[1]),"r"(a[2]),"r"(a[3]), "r"(b[0]),"r"(b[1]));
}
__device__ __forceinline__ void mmaf8(float* c, const uint32_t* a, const uint32_t* b){
    asm volatile("mma.sync.aligned.m16n8k32.row.col.f32.e4m3.e4m3.f32 "
        "{%0,%1,%2,%3}, {%4,%5,%6,%7}, {%8,%9}, {%0,%1,%2,%3};"
        : "+f"(c[0]),"+f"(c[1]),"+f"(c[2]),"+f"(c[3])
        : "r"(a[0]),"r"(a[1]),"r"(a[2]),"r"(a[3]), "r"(b[0]),"r"(b[1]));
}
__device__ __forceinline__ void cpa16(uint32_t s, const void* g){
    asm volatile("cp.async.cg.shared.global [%0], [%1], 16;" :: "r"(s), "l"(g));
}
#define CPA_COMMIT() asm volatile("cp.async.commit_group;" ::: "memory")
#define CPA_WAIT1()  asm volatile("cp.async.wait_group 1;" ::: "memory")
#define CPA_WAIT0()  asm volatile("cp.async.wait_group 0;" ::: "memory")

// ---- warp-tile compute: bf16 hi*hi + fp8 corrections (K=32 chunk) ----
// bf16 tiles: stride 80B. fp8 tiles: stride 48B (conflict-free).
template<int WNT>
__device__ __forceinline__ void tile_f8(
    uint32_t aAh, uint32_t aA8h, uint32_t aA8l,
    uint32_t aBh, uint32_t aB8h, uint32_t aB8l,
    int wm, int wn, int lane, float c[4][WNT][4], float c2[4][WNT][4])
{
    const int ar = wm*64 + (lane & 15);
    const int br = wn*(WNT*8) + (lane & 7);
#pragma unroll
    for (int h = 0; h < 2; h++) {
        uint32_t fA[4][4], fB[WNT][2];
        const int ac = h*16 + ((lane >> 4) << 3);
        const int bc = h*16 + ((lane >> 3) & 1)*8;
#pragma unroll
        for (int mi = 0; mi < 4; mi++)
            ldmx4(fA[mi], aAh + (uint32_t)((ar + mi*16)*40 + ac)*2);
#pragma unroll
        for (int ni = 0; ni < WNT; ni++)
            ldmx2(fB[ni], aBh + (uint32_t)((br + ni*8)*40 + bc)*2);
#pragma unroll
        for (int mi = 0; mi < 4; mi++)
#pragma unroll
            for (int ni = 0; ni < WNT; ni++)
                mma16816(c[mi][ni], fA[mi], fB[ni]);
    }
    {
        uint32_t fAh8[4][4], fAl8[4][4], fBh8[WNT][2], fBl8[WNT][2];
        const int ac8 = (lane >> 4) * 16;
        const int bc8 = ((lane >> 3) & 1) * 16;
#pragma unroll
        for (int mi = 0; mi < 4; mi++) {
            uint32_t ro = (uint32_t)(ar + mi*16)*48 + ac8;
            ldmx4(fAh8[mi], aA8h + ro);
            ldmx4(fAl8[mi], aA8l + ro);
        }
#pragma unroll
        for (int ni = 0; ni < WNT; ni++) {
            uint32_t ro = (uint32_t)(br + ni*8)*48 + bc8;
            ldmx2(fBh8[ni], aB8h + ro);
            ldmx2(fBl8[ni], aB8l + ro);
        }
#pragma unroll
        for (int mi = 0; mi < 4; mi++)
#pragma unroll
            for (int ni = 0; ni < WNT; ni++) {
                mmaf8(c2[mi][ni], fAh8[mi], fBl8[ni]);
                mmaf8(c2[mi][ni], fAl8[mi], fBh8[ni]);
            }
    }
}

// ---- fused split: x -> bf16 hi + fp8(hi) + fp8(lo*256); grid.y = tensor ----
__global__ void split_kernel(const float* __restrict__ x0,
                             const float* __restrict__ x1,
                             const float* __restrict__ x2,
                             __nv_bfloat16* __restrict__ xh,
                             uint8_t* __restrict__ x8h, uint8_t* __restrict__ x8l)
{
    const int z = blockIdx.y;
    const float* x = (z == 0) ? x0 : (z == 1) ? x1 : x2;
    const size_t off = (size_t)z * MT * DIM;
    int i = (blockIdx.x * blockDim.x + threadIdx.x) * 4;
    float4 v = *(const float4*)&x[i];
    __nv_bfloat16 h0 = __float2bfloat16(v.x), h1 = __float2bfloat16(v.y);
    __nv_bfloat16 h2 = __float2bfloat16(v.z), h3 = __float2bfloat16(v.w);
    uint2 hp = { pk2(h0,h1), pk2(h2,h3) };
    *(uint2*)&xh[off + i] = hp;
    *(uint32_t*)&x8h[off + i] = pk8x4(f2e4(v.x), f2e4(v.y), f2e4(v.z), f2e4(v.w));
    *(uint32_t*)&x8l[off + i] = pk8x4(
        f2e4((v.x - __bfloat162float(h0))*256.f),
        f2e4((v.y - __bfloat162float(h1))*256.f),
        f2e4((v.z - __bfloat162float(h2))*256.f),
        f2e4((v.w - __bfloat162float(h3))*256.f));
}

// ---- W[K,N] -> WT[N,K]: bf16 hi + fp8 hi + fp8 lo*256 ----
__global__ void wtrans_kernel(const float* __restrict__ W,
                              __nv_bfloat16* __restrict__ Th,
                              uint8_t* __restrict__ T8h, uint8_t* __restrict__ T8l)
{
    __shared__ float t[32][33];
    int bx = blockIdx.x * 32, by = blockIdx.y * 32;
    int x = threadIdx.x, y = threadIdx.y;
    for (int yy = y; yy < 32; yy += 8)
        t[yy][x] = W[(size_t)(by + yy) * DIM + bx + x];
    __syncthreads();
    for (int yy = y; yy < 32; yy += 8) {
        float v = t[x][yy];
        __nv_bfloat16 h = __float2bfloat16(v);
        size_t o = (size_t)(bx + yy) * DIM + by + x;
        Th[o]  = h;
        T8h[o] = f2e4(v);
        T8l[o] = f2e4((v - __bfloat162float(h))*256.f);
    }
}

// ---- V [bh,s,d] -> VT [bh,d,s]; z: 0 bf16, 1 fp8h, 2 fp8l ----
__global__ void vtrans_kernel(const __nv_bfloat16* __restrict__ Vh,
                              const uint8_t* __restrict__ V8h,
                              const uint8_t* __restrict__ V8l,
                              __nv_bfloat16* __restrict__ VTh,
                              uint8_t* __restrict__ VT8h,
                              uint8_t* __restrict__ VT8l)
{
    __shared__ __nv_bfloat16 tb[64][65];
    __shared__ uint8_t t8[64][65];
    const int z = blockIdx.z;
    int bh = blockIdx.y, s0 = blockIdx.x * 64;
    int tid = threadIdx.x;
    if (z == 0) {
        for (int i = tid; i < 64*64; i += 256) {
            int r = i >> 6, cc = i & 63;
            tb[r][cc] = Vh[((size_t)bh*SS + s0 + r)*DD + cc];
        }
        __syncthreads();
        for (int i = tid; i < 64*64; i += 256) {
            int r = i >> 6, cc = i & 63;
            VTh[((size_t)bh*DD + r)*SS + s0 + cc] = tb[cc][r];
        }
    } else {
        const uint8_t* S = (z == 1) ? V8h : V8l;
        uint8_t* D = (z == 1) ? VT8h : VT8l;
        for (int i = tid; i < 64*64; i += 256) {
            int r = i >> 6, cc = i & 63;
            t8[r][cc] = S[((size_t)bh*SS + s0 + r)*DD + cc];
        }
        __syncthreads();
        for (int i = tid; i < 64*64; i += 256) {
            int r = i >> 6, cc = i & 63;
            D[((size_t)bh*DD + r)*SS + s0 + cc] = t8[cc][r];
        }
    }
}

// ===========================================================================
// Projection GEMMs (cp.async 2-stage, fp8 corrections).
// MODE 0 QKV (z=0..2, +bias, split-head trio out), MODE 1 out-proj (+bias, fp32)
// dyn smem = 90112
// ===========================================================================
template<int MODE>
__global__ __launch_bounds__(256) void gemm_pipe_kernel(
    const __nv_bfloat16* __restrict__ Ah_, const uint8_t* __restrict__ A8h_,
    const uint8_t* __restrict__ A8l_,
    const __nv_bfloat16* __restrict__ Bh_, const uint8_t* __restrict__ B8h_,
    const uint8_t* __restrict__ B8l_,
    const float* __restrict__ b0, const float* __restrict__ b1, const float* __restrict__ b2,
    float* __restrict__ outF,
    __nv_bfloat16* __restrict__ Oh_, uint8_t* __restrict__ O8h_, uint8_t* __restrict__ O8l_)
{
    constexpr int NT = 32;
    extern __shared__ char sm[];
    const uint32_t sb = s2u(sm);
    const uint32_t aAH[2]  = { sb,          sb + 10240 };
    const uint32_t aBH[2]  = { sb + 20480,  sb + 30720 };
    const uint32_t aA8H[2] = { sb + 40960,  sb + 47104 };
    const uint32_t aA8L[2] = { sb + 53248,  sb + 59392 };
    const uint32_t aB8H[2] = { sb + 65536,  sb + 71680 };
    const uint32_t aB8L[2] = { sb + 77824,  sb + 83968 };

    const int tid = threadIdx.x, lane = tid & 31, wid = tid >> 5;
    const int wm = wid >> 2, wn = wid & 3;
    const size_t NX = (size_t)MT * DIM, NW = (size_t)DIM * DIM;

    const int z  = (MODE == 0) ? blockIdx.z : 0;
    const int n0 = blockIdx.x*128, m0 = blockIdx.y*128;

    const __nv_bfloat16* Abh = (MODE == 0 ? Ah_ + z*NX : Ah_) + (size_t)m0 * DIM;
    const uint8_t* A8h = (MODE == 0 ? A8h_ + z*NX : A8h_) + (size_t)m0 * DIM;
    const uint8_t* A8l = (MODE == 0 ? A8l_ + z*NX : A8l_) + (size_t)m0 * DIM;
    const __nv_bfloat16* Bbh = (MODE == 0 ? Bh_ + z*NW : Bh_) + (size_t)n0 * DIM;
    const uint8_t* B8h = (MODE == 0 ? B8h_ + z*NW : B8h_) + (size_t)n0 * DIM;
    const uint8_t* B8l = (MODE == 0 ? B8l_ + z*NW : B8l_) + (size_t)n0 * DIM;
    const float* bias = (MODE == 0) ? (z == 0 ? b0 : (z == 1 ? b1 : b2)) : b0;

    float c[4][4][4] = {};
    float c2[4][4][4] = {};

    auto load_stage = [&](int st, int k0){
        for (int idx = tid; idx < 512; idx += 256) {
            int r = idx >> 2, cc = idx & 3;
            uint32_t so = (uint32_t)r*80 + cc*16;
            size_t go = (size_t)r*DIM + k0 + cc*8;
            cpa16(aAH[st] + so, Abh + go);
            cpa16(aBH[st] + so, Bbh + go);
        }
        for (int idx = tid; idx < 256; idx += 256) {
            int r = idx >> 1, cc = idx & 1;
            uint32_t so = (uint32_t)r*48 + cc*16;
            size_t go = (size_t)r*DIM + k0 + cc*16;
            cpa16(aA8H[st] + so, A8h + go);
            cpa16(aA8L[st] + so, A8l + go);
            cpa16(aB8H[st] + so, B8h + go);
            cpa16(aB8L[st] + so, B8l + go);
        }
    };

    load_stage(0, 0);  CPA_COMMIT();
    load_stage(1, 32); CPA_COMMIT();

    for (int kt = 0; kt < NT; kt++) {
        if (kt + 1 < NT) { CPA_WAIT1(); } else { CPA_WAIT0(); }
        __syncthreads();
        const int st = kt & 1;
        tile_f8<4>(aAH[st], aA8H[st], aA8L[st], aBH[st], aB8H[st], aB8L[st],
                   wm, wn, lane, c, c2);
        __syncthreads();
        if (kt + 2 < NT) { load_stage(st, (kt + 2) * 32); CPA_COMMIT(); }
    }

    const int g = lane >> 2, tg = lane & 3;
#pragma unroll
    for (int mi = 0; mi < 4; mi++)
#pragma unroll
        for (int ni = 0; ni < 4; ni++) {
            const int m = m0 + wm*64 + mi*16 + g;
            const int n = n0 + wn*32 + ni*8 + tg*2;
            const float q0 = bias[n], q1 = bias[n+1];
            const float v00 = c[mi][ni][0] + c2[mi][ni][0]*0.00390625f + q0;
            const float v01 = c[mi][ni][1] + c2[mi][ni][1]*0.00390625f + q1;
            const float v10 = c[mi][ni][2] + c2[mi][ni][2]*0.00390625f + q0;
            const float v11 = c[mi][ni][3] + c2[mi][ni][3]*0.00390625f + q1;
            if (MODE == 1) {
                float2 r0 = { v00, v01 };
                float2 r1 = { v10, v11 };
                *(float2*)&outF[(size_t)m*DIM + n]     = r0;
                *(float2*)&outF[(size_t)(m+8)*DIM + n] = r1;
            } else {
                const int b = m >> 11, hd = n >> 6, d = n & 63;
                const size_t base = z*NX + (((size_t)(b*HH + hd))*SS + (m & 2047))*DD + d;
                __nv_bfloat16 h0 = __float2bfloat16(v00), h1 = __float2bfloat16(v01);
                __nv_bfloat16 h2 = __float2bfloat16(v10), h3 = __float2bfloat16(v11);
                *(uint32_t*)&Oh_[base]        = pk2(h0, h1);
                *(uint32_t*)&Oh_[base + 8*DD] = pk2(h2, h3);
                *(uint16_t*)&O8h_[base] =
                    (uint16_t)f2e4(v00) | ((uint16_t)f2e4(v01) << 8);
                *(uint16_t*)&O8h_[base + 8*DD] =
                    (uint16_t)f2e4(v10) | ((uint16_t)f2e4(v11) << 8);
                *(uint16_t*)&O8l_[base] =
                    (uint16_t)f2e4((v00 - __bfloat162float(h0))*256.f) |
                    ((uint16_t)f2e4((v01 - __bfloat162float(h1))*256.f) << 8);
                *(uint16_t*)&O8l_[base + 8*DD] =
                    (uint16_t)f2e4((v10 - __bfloat162float(h2))*256.f) |
                    ((uint16_t)f2e4((v11 - __bfloat162float(h3))*256.f) << 8);
            }
        }
}

// ===========================================================================
// Logits fused (fp8 corrections): QK^T, scale+bias+mask epilogue, biased
// logits + per-stile partials. grid (16,16,32). dyn 90112.
// ===========================================================================
__global__ __launch_bounds__(256) void logits_fused_kernel(
    const __nv_bfloat16* __restrict__ Qh, const uint8_t* __restrict__ Q8h,
    const uint8_t* __restrict__ Q8l,
    const __nv_bfloat16* __restrict__ Kh, const uint8_t* __restrict__ K8h,
    const uint8_t* __restrict__ K8l,
    const float* __restrict__ bias4d, const float* __restrict__ pad,
    float* __restrict__ attn, float2* __restrict__ part)
{
    extern __shared__ char sm[];
    const uint32_t sb = s2u(sm);
    const uint32_t aAH[2]  = { sb,          sb + 10240 };
    const uint32_t aBH[2]  = { sb + 20480,  sb + 30720 };
    const uint32_t aA8H[2] = { sb + 40960,  sb + 47104 };
    const uint32_t aA8L[2] = { sb + 53248,  sb + 59392 };
    const uint32_t aB8H[2] = { sb + 65536,  sb + 71680 };
    const uint32_t aB8L[2] = { sb + 77824,  sb + 83968 };

    const int tid = threadIdx.x, lane = tid & 31, wid = tid >> 5;
    const int wm = wid >> 2, wn = wid & 3;
    const int bh = blockIdx.z, b = bh >> 4;
    const int stile = blockIdx.x;
    const int n0 = stile*128, m0 = blockIdx.y*128;

    const size_t aro = ((size_t)bh*SS + m0) * DD;
    const size_t bro = ((size_t)bh*SS + n0) * DD;

    auto load_stage = [&](int st, int k0){
        for (int idx = tid; idx < 512; idx += 256) {
            int r = idx >> 2, cc = idx & 3;
            uint32_t so = (uint32_t)r*80 + cc*16;
            size_t go = (size_t)r*DD + k0 + cc*8;
            cpa16(aAH[st] + so, Qh + aro + go);
            cpa16(aBH[st] + so, Kh + bro + go);
        }
        for (int idx = tid; idx < 256; idx += 256) {
            int r = idx >> 1, cc = idx & 1;
            uint32_t so = (uint32_t)r*48 + cc*16;
            size_t go = (size_t)r*DD + k0 + cc*16;
            cpa16(aA8H[st] + so, Q8h + aro + go);
            cpa16(aA8L[st] + so, Q8l + aro + go);
            cpa16(aB8H[st] + so, K8h + bro + go);
            cpa16(aB8L[st] + so, K8l + bro + go);
        }
    };

    load_stage(0, 0);  CPA_COMMIT();
    load_stage(1, 32); CPA_COMMIT();

    float c[4][4][4] = {};
    float c2[4][4][4] = {};
    CPA_WAIT1();
    __syncthreads();
    tile_f8<4>(aAH[0], aA8H[0], aA8L[0], aBH[0], aB8H[0], aB8L[0], wm, wn, lane, c, c2);
    CPA_WAIT0();
    __syncthreads();
    tile_f8<4>(aAH[1], aA8H[1], aA8L[1], aBH[1], aB8H[1], aB8L[1], wm, wn, lane, c, c2);
    __syncthreads();

    float2* spair = (float2*)sm;
    const int g = lane >> 2, tg = lane & 3;

#pragma unroll
    for (int mi = 0; mi < 4; mi++)
#pragma unroll
        for (int half = 0; half < 2; half++) {
            const int rloc = wm*64 + mi*16 + half*8 + g;
            const int t = m0 + rloc;
            const float mt = 1.0f - pad[b*SS + t];
            const float* bp = &bias4d[((size_t)bh*SS + t)*SS + n0];
            float* ap = &attn[((size_t)bh*SS + t)*SS + n0];
            float vv[8];
#pragma unroll
            for (int ni = 0; ni < 4; ni++) {
                const int nl = wn*32 + ni*8 + tg*2;
                const float ms0 = 1.0f - pad[b*SS + n0 + nl];
                const float ms1 = 1.0f - pad[b*SS + n0 + nl + 1];
                float d0 = c[mi][ni][half*2+0] + c2[mi][ni][half*2+0]*0.00390625f;
                float d1 = c[mi][ni][half*2+1] + c2[mi][ni][half*2+1]*0.00390625f;
                float x0 = d0*0.125f + bp[nl]   - 1e9f*(1.0f - mt*ms0);
                float x1 = d1*0.125f + bp[nl+1] - 1e9f*(1.0f - mt*ms1);
                vv[ni*2]   = x0;
                vv[ni*2+1] = x1;
                float2 w = { x0, x1 };
                *(float2*)&ap[nl] = w;
            }
            float mx = vv[0];
#pragma unroll
            for (int j = 1; j < 8; j++) mx = fmaxf(mx, vv[j]);
            mx = fmaxf(mx, __shfl_xor_sync(~0u, mx, 1));
            mx = fmaxf(mx, __shfl_xor_sync(~0u, mx, 2));
            float se = 0.f;
#pragma unroll
            for (int j = 0; j < 8; j++) se += __expf(vv[j] - mx);
            se += __shfl_xor_sync(~0u, se, 1);
            se += __shfl_xor_sync(~0u, se, 2);
            if (tg == 0) spair[wn*128 + rloc] = make_float2(mx, se);
        }
    __syncthreads();

    if (tid < 128) {
        float2 p0 = spair[tid], p1 = spair[128 + tid];
        float2 p2 = spair[256 + tid], p3 = spair[384 + tid];
        float m01 = fmaxf(p0.x, p1.x), m23 = fmaxf(p2.x, p3.x);
        float m = fmaxf(m01, m23);
        float s = p0.y*__expf(p0.x - m) + p1.y*__expf(p1.x - m)
                + p2.y*__expf(p2.x - m) + p3.y*__expf(p3.x - m);
        part[(((size_t)bh*SS) + m0 + tid)*16 + stile] = make_float2(m, s);
    }
}

// ---- merge 16 partials per row -> (max, 1/sum) ----
__global__ void ms_reduce_kernel(const float2* __restrict__ part,
                                 float2* __restrict__ ms)
{
    const int row = blockIdx.x * 256 + threadIdx.x;
    const float2* p = part + (size_t)row * 16;
    float2 v[16];
#pragma unroll
    for (int i = 0; i < 8; i++) {
        float4 a = *(const float4*)&p[i*2];
        v[i*2]   = make_float2(a.x, a.y);
        v[i*2+1] = make_float2(a.z, a.w);
    }
    float m = v[0].x;
#pragma unroll
    for (int i = 1; i < 16; i++) m = fmaxf(m, v[i].x);
    float s = 0.f;
#pragma unroll
    for (int i = 0; i < 16; i++) s += v[i].y * __expf(v[i].x - m);
    ms[row] = make_float2(m, 1.0f / s);
}

// ===========================================================================
// AV fused (fp8 corrections): normalize + write weights + convert + MMA.
// grid (16,32). dyn smem 82944.
// ===========================================================================
__global__ __launch_bounds__(256) void av_pipe_kernel(
    float* __restrict__ attn,
    const float2* __restrict__ ms,
    const __nv_bfloat16* __restrict__ VTh, const uint8_t* __restrict__ VT8h,
    const uint8_t* __restrict__ VT8l,
    __nv_bfloat16* __restrict__ Ch, uint8_t* __restrict__ C8h, uint8_t* __restrict__ C8l)
{
    extern __shared__ char sm[];
    const uint32_t sb = s2u(sm);
    const uint32_t aAF[2]  = { sb, sb + 18432 };
    const uint32_t aWH     = sb + 36864;        // bf16 128x(40e), stride 80B
    const uint32_t aW8H    = sb + 47104;        // fp8 128x48B
    const uint32_t aW8L    = sb + 53248;
    const uint32_t aBH[2]  = { sb + 59392, sb + 64512 };
    const uint32_t aB8H[2] = { sb + 69632, sb + 72704 };
    const uint32_t aB8L[2] = { sb + 75776, sb + 78848 };
    float2* sms = (float2*)(sm + 81920);

    const int tid = threadIdx.x, lane = tid & 31, wid = tid >> 5;
    const int wm = wid >> 2, wn = wid & 3;
    const int bh = blockIdx.y, b = bh >> 4, hd = bh & 15;
    const int m0 = blockIdx.x * 128;

    float* Abf = attn + ((size_t)bh*SS + m0) * SS;
    const size_t bro = (size_t)bh*DD*SS;

    if (tid < 128) sms[tid] = ms[(size_t)bh*SS + m0 + tid];

    float c[4][2][4] = {};
    float c2[4][2][4] = {};

    auto load_stage = [&](int st, int k0){
        for (int idx = tid; idx < 1024; idx += 256) {
            int r = idx >> 3, cc = idx & 7;
            cpa16(aAF[st] + (uint32_t)r*144 + cc*16, Abf + (size_t)r*SS + k0 + cc*4);
        }
        for (int idx = tid; idx < 256; idx += 256) {
            int r = idx >> 2, cc = idx & 3;
            cpa16(aBH[st] + (uint32_t)r*80 + cc*16, VTh + bro + (size_t)r*SS + k0 + cc*8);
        }
        for (int idx = tid; idx < 128; idx += 256) {
            int r = idx >> 1, cc = idx & 1;
            uint32_t so = (uint32_t)r*48 + cc*16;
            size_t go = bro + (size_t)r*SS + k0 + cc*16;
            cpa16(aB8H[st] + so, VT8h + go);
            cpa16(aB8L[st] + so, VT8l + go);
        }
    };

    load_stage(0, 0);  CPA_COMMIT();
    load_stage(1, 32); CPA_COMMIT();

    for (int kt = 0; kt < 64; kt++) {
        if (kt + 1 < 64) { CPA_WAIT1(); } else { CPA_WAIT0(); }
        __syncthreads();
        const int st = kt & 1;
        const int k0 = kt * 32;
        for (int idx = tid; idx < 1024; idx += 256) {
            int r = idx >> 3, cc = idx & 7;
            float4 w = *(const float4*)(sm + st*18432 + r*144 + cc*16);
            float2 q = sms[r];
            w.x = __expf(w.x - q.x) * q.y;
            w.y = __expf(w.y - q.x) * q.y;
            w.z = __expf(w.z - q.x) * q.y;
            w.w = __expf(w.w - q.x) * q.y;
            *(float4*)&Abf[(size_t)r*SS + k0 + cc*4] = w;
            __nv_bfloat16 h0 = __float2bfloat16(w.x), h1 = __float2bfloat16(w.y);
            __nv_bfloat16 h2 = __float2bfloat16(w.z), h3 = __float2bfloat16(w.w);
            uint2 hp = { pk2(h0,h1), pk2(h2,h3) };
            *(uint2*)(sm + 36864 + r*80 + cc*8) = hp;
            *(uint32_t*)(sm + 47104 + r*48 + cc*4) =
                pk8x4(f2e4(w.x), f2e4(w.y), f2e4(w.z), f2e4(w.w));
            *(uint32_t*)(sm + 53248 + r*48 + cc*4) = pk8x4(
                f2e4((w.x - __bfloat162float(h0))*256.f),
                f2e4((w.y - __bfloat162float(h1))*256.f),
                f2e4((w.z - __bfloat162float(h2))*256.f),
                f2e4((w.w - __bfloat162float(h3))*256.f));
        }
        __syncthreads();
        tile_f8<2>(aWH, aW8H, aW8L, aBH[st], aB8H[st], aB8L[st], wm, wn, lane, c, c2);
        __syncthreads();
        if (kt + 2 < 64) { load_stage(st, (kt + 2) * 32); CPA_COMMIT(); }
    }

    const int g = lane >> 2, tg = lane & 3;
#pragma unroll
    for (int mi = 0; mi < 4; mi++)
#pragma unroll
        for (int ni = 0; ni < 2; ni++) {
            const int m = m0 + wm*64 + mi*16 + g;
            const int n = wn*16 + ni*8 + tg*2;
            const size_t base = ((size_t)(b*SS + m))*DIM + hd*DD + n;
            const float v00 = c[mi][ni][0] + c2[mi][ni][0]*0.00390625f;
            const float v01 = c[mi][ni][1] + c2[mi][ni][1]*0.00390625f;
            const float v10 = c[mi][ni][2] + c2[mi][ni][2]*0.00390625f;
            const float v11 = c[mi][ni][3] + c2[mi][ni][3]*0.00390625f;
            __nv_bfloat16 h0 = __float2bfloat16(v00), h1 = __float2bfloat16(v01);
            __nv_bfloat16 h2 = __float2bfloat16(v10), h3 = __float2bfloat16(v11);
            *(uint32_t*)&Ch[base]         = pk2(h0, h1);
            *(uint32_t*)&Ch[base + 8*DIM] = pk2(h2, h3);
            *(uint16_t*)&C8h[base] = (uint16_t)f2e4(v00) | ((uint16_t)f2e4(v01) << 8);
            *(uint16_t*)&C8h[base + 8*DIM] = (uint16_t)f2e4(v10) | ((uint16_t)f2e4(v11) << 8);
            *(uint16_t*)&C8l[base] =
                (uint16_t)f2e4((v00 - __bfloat162float(h0))*256.f) |
                ((uint16_t)f2e4((v01 - __bfloat162float(h1))*256.f) << 8);
            *(uint16_t*)&C8l[base + 8*DIM] =
                (uint16_t)f2e4((v10 - __bfloat162float(h2))*256.f) |
                ((uint16_t)f2e4((v11 - __bfloat162float(h3))*256.f) << 8);
        }
}

// ---------------------------------------------------------------------------
extern "C" void kernel_launch(void* const* d_in, const int* in_sizes, int n_in,
                              void* d_out, int out_size)
{
    const float* attnbias = (const float*)d_in[3];
    const float* paddings = (const float*)d_in[4];
    const float* ww[4] = { (const float*)d_in[5], (const float*)d_in[7],
                           (const float*)d_in[9], (const float*)d_in[11] };
    const float* wb[4] = { (const float*)d_in[6], (const float*)d_in[8],
                           (const float*)d_in[10], (const float*)d_in[12] };

    float* out  = (float*)d_out;
    float* attn = out + (size_t)MT * DIM;

    __nv_bfloat16 *xh, *twh, *ph, *vth, *ch;
    uint8_t *x8h, *x8l, *tw8h, *tw8l, *p8h, *p8l, *vt8h, *vt8l, *c8h, *c8l;
    float2 *partp, *msp;
    cudaGetSymbolAddress((void**)&xh, g_xh);
    cudaGetSymbolAddress((void**)&x8h, g_x8h);   cudaGetSymbolAddress((void**)&x8l, g_x8l);
    cudaGetSymbolAddress((void**)&twh, g_twh);
    cudaGetSymbolAddress((void**)&tw8h, g_tw8h); cudaGetSymbolAddress((void**)&tw8l, g_tw8l);
    cudaGetSymbolAddress((void**)&ph, g_ph);
    cudaGetSymbolAddress((void**)&p8h, g_p8h);   cudaGetSymbolAddress((void**)&p8l, g_p8l);
    cudaGetSymbolAddress((void**)&vth, g_vth);
    cudaGetSymbolAddress((void**)&vt8h, g_vt8h); cudaGetSymbolAddress((void**)&vt8l, g_vt8l);
    cudaGetSymbolAddress((void**)&ch, g_ch);
    cudaGetSymbolAddress((void**)&c8h, g_c8h);   cudaGetSymbolAddress((void**)&c8l, g_c8l);
    cudaGetSymbolAddress((void**)&partp, g_part); cudaGetSymbolAddress((void**)&msp, g_ms);

    static int attr_done = 0;
    if (!attr_done) {
        cudaFuncSetAttribute(gemm_pipe_kernel<0>,  cudaFuncAttributeMaxDynamicSharedMemorySize, 90112);
        cudaFuncSetAttribute(gemm_pipe_kernel<1>,  cudaFuncAttributeMaxDynamicSharedMemorySize, 90112);
        cudaFuncSetAttribute(logits_fused_kernel,  cudaFuncAttributeMaxDynamicSharedMemorySize, 90112);
        cudaFuncSetAttribute(av_pipe_kernel,       cudaFuncAttributeMaxDynamicSharedMemorySize, 82944);
        attr_done = 1;
    }

    const size_t NX = (size_t)MT * DIM;
    const size_t NW = (size_t)DIM * DIM;

    split_kernel<<<dim3(NX/1024, 3), 256>>>(
        (const float*)d_in[0], (const float*)d_in[1], (const float*)d_in[2],
        xh, x8h, x8l);
    for (int i = 0; i < 4; i++)
        wtrans_kernel<<<dim3(32,32), dim3(32,8)>>>(ww[i], twh + i*NW,
                                                   tw8h + i*NW, tw8l + i*NW);

    // QKV projections, batched
    gemm_pipe_kernel<0><<<dim3(8,32,3), 256, 90112>>>(
        xh, x8h, x8l, twh, tw8h, tw8l, wb[0], wb[1], wb[2],
        nullptr, ph, p8h, p8l);

    __nv_bfloat16 *qh = ph, *kh = ph + NX, *vh = ph + 2*NX;
    uint8_t *q8h = p8h, *k8h = p8h + NX, *v8h = p8h + 2*NX;
    uint8_t *q8l = p8l, *k8l = p8l + NX, *v8l = p8l + 2*NX;

    // V transpose (bf16 + 2 fp8) in one launch
    vtrans_kernel<<<dim3(32, NBH, 3), 256>>>(vh, v8h, v8l, vth, vt8h, vt8l);

    // logits + bias + mask + softmax partials
    logits_fused_kernel<<<dim3(16,16,NBH), 256, 90112>>>(
        qh, q8h, q8l, kh, k8h, k8l, attnbias, paddings, attn, partp);

    ms_reduce_kernel<<<(NBH*SS)/256, 256>>>(partp, msp);

    // AV: normalize + write weights + MMA
    av_pipe_kernel<<<dim3(16, NBH), 256, 82944>>>(
        attn, msp, vth, vt8h, vt8l, ch, c8h, c8l);

    // output projection -> fp32 out
    gemm_pipe_kernel<1><<<dim3(8,32), 256, 90112>>>(
        ch, c8h, c8l, twh + 3*NW, tw8h + 3*NW, tw8l + 3*NW, wb[3],
        nullptr, nullptr, out, nullptr, nullptr, nullptr);
}

// round 14
// speedup vs baseline: 1.2314x; 1.2314x over previous
#include <cuda_runtime.h>
#include <cuda_bf16.h>
#include <stdint.h>

#define BB  2
#define SS  2048
#define DIM 1024
#define HH  16
#define DD  64
#define MT  (BB*SS)
#define NBH (BB*HH)

// ---- device scratch ----
__device__ __nv_bfloat16 g_xh[3][MT*DIM], g_xl[3][MT*DIM];
__device__ __nv_bfloat16 g_twh[4][DIM*DIM], g_twl[4][DIM*DIM];
__device__ __nv_bfloat16 g_ph[3][NBH*SS*DD], g_pl[3][NBH*SS*DD];
__device__ __nv_bfloat16 g_vth[NBH*DD*SS], g_vtl[NBH*DD*SS];
__device__ __nv_bfloat16 g_ch[MT*DIM], g_cl[MT*DIM];
__device__ float2 g_part[(size_t)NBH*SS*16];
__device__ float2 g_ms[(size_t)NBH*SS];

#define STRD 40

// ---- helpers ----
__device__ __forceinline__ uint32_t s2u(const void* p){
    uint32_t a;
    asm("{ .reg .u64 t; cvta.to.shared.u64 t, %1; cvt.u32.u64 %0, t; }":"=r"(a):"l"(p));
    return a;
}
__device__ __forceinline__ void bsplit(float v, __nv_bfloat16& h, __nv_bfloat16& l){
    h = __float2bfloat16(v);
    l = __float2bfloat16(v - __bfloat162float(h));
}
__device__ __forceinline__ uint32_t pk2(__nv_bfloat16 a, __nv_bfloat16 b){
    __nv_bfloat162 t(a, b); return *(uint32_t*)&t;
}
__device__ __forceinline__ void ldmx4(uint32_t* r, uint32_t addr){
    asm volatile("ldmatrix.sync.aligned.m8n8.x4.shared.b16 {%0,%1,%2,%3}, [%4];"
        : "=r"(r[0]),"=r"(r[1]),"=r"(r[2]),"=r"(r[3]) : "r"(addr));
}
__device__ __forceinline__ void ldmx2(uint32_t* r, uint32_t addr){
    asm volatile("ldmatrix.sync.aligned.m8n8.x2.shared.b16 {%0,%1}, [%2];"
        : "=r"(r[0]),"=r"(r[1]) : "r"(addr));
}
__device__ __forceinline__ void mma16816(float* c, const uint32_t* a, const uint32_t* b){
    asm volatile("mma.sync.aligned.m16n8k16.row.col.f32.bf16.bf16.f32 "
        "{%0,%1,%2,%3}, {%4,%5,%6,%7}, {%8,%9}, {%0,%1,%2,%3};"
        : "+f"(c[0]),"+f"(c[1]),"+f"(c[2]),"+f"(c[3])
        : "r"(a[0]),"r"(a[1]),"r"(a[2]),"r"(a[3]), "r"(b[0]),"r"(b[1]));
}
__device__ __forceinline__ void cpa16(uint32_t s, const void* g){
    asm volatile("cp.async.cg.shared.global [%0], [%1], 16;" :: "r"(s), "l"(g));
}
#define CPA_COMMIT() asm volatile("cp.async.commit_group;" ::: "memory")
#define CPA_WAIT1()  asm volatile("cp.async.wait_group 1;" ::: "memory")
#define CPA_WAIT0()  asm volatile("cp.async.wait_group 0;" ::: "memory")

// ---- warp-tile compute ----
template<int WNT>
__device__ __forceinline__ void tile_compute(
    uint32_t aAh, uint32_t aAl, uint32_t aBh, uint32_t aBl,
    int wm, int wn, int lane, float c[4][WNT][4])
{
#pragma unroll
    for (int h = 0; h < 2; h++) {
        uint32_t fAh[4][4], fAl[4][4], fBh[WNT][2], fBl[WNT][2];
        const int ar = wm*64 + (lane & 15);
        const int ac = h*16 + ((lane >> 4) << 3);
#pragma unroll
        for (int mi = 0; mi < 4; mi++) {
            uint32_t off = (uint32_t)((ar + mi*16)*STRD + ac) * 2;
            ldmx4(fAh[mi], aAh + off);
            ldmx4(fAl[mi], aAl + off);
        }
        const int br = wn*(WNT*8) + (lane & 7);
        const int bc = h*16 + ((lane >> 3) & 1)*8;
#pragma unroll
        for (int ni = 0; ni < WNT; ni++) {
            uint32_t off = (uint32_t)((br + ni*8)*STRD + bc) * 2;
            ldmx2(fBh[ni], aBh + off);
            ldmx2(fBl[ni], aBl + off);
        }
#pragma unroll
        for (int mi = 0; mi < 4; mi++)
#pragma unroll
            for (int ni = 0; ni < WNT; ni++) {
                mma16816(c[mi][ni], fAh[mi], fBh[ni]);
                mma16816(c[mi][ni], fAh[mi], fBl[ni]);
                mma16816(c[mi][ni], fAl[mi], fBh[ni]);
            }
    }
}

// ---- fp32 -> bf16 hi/lo split ----
__global__ void split_kernel(const float* __restrict__ x,
                             __nv_bfloat16* __restrict__ h,
                             __nv_bfloat16* __restrict__ l)
{
    int i = (blockIdx.x * blockDim.x + threadIdx.x) * 4;
    float4 v = *(const float4*)&x[i];
    __nv_bfloat16 h0,h1,h2,h3,l0,l1,l2,l3;
    bsplit(v.x,h0,l0); bsplit(v.y,h1,l1); bsplit(v.z,h2,l2); bsplit(v.w,h3,l3);
    uint2 hp = { pk2(h0,h1), pk2(h2,h3) };
    uint2 lp = { pk2(l0,l1), pk2(l2,l3) };
    *(uint2*)&h[i] = hp; *(uint2*)&l[i] = lp;
}

// ---- W[K,N] -> WT[N,K] hi/lo ----
__global__ void wtrans_kernel(const float* __restrict__ W,
                              __nv_bfloat16* __restrict__ Th,
                              __nv_bfloat16* __restrict__ Tl)
{
    __shared__ float t[32][33];
    int bx = blockIdx.x * 32, by = blockIdx.y * 32;
    int x = threadIdx.x, y = threadIdx.y;
    for (int yy = y; yy < 32; yy += 8)
        t[yy][x] = W[(size_t)(by + yy) * DIM + bx + x];
    __syncthreads();
    for (int yy = y; yy < 32; yy += 8) {
        __nv_bfloat16 h, l; bsplit(t[x][yy], h, l);
        Th[(size_t)(bx + yy) * DIM + by + x] = h;
        Tl[(size_t)(bx + yy) * DIM + by + x] = l;
    }
}

// ---- V [bh,s,d] -> VT [bh,d,s] (bf16) ----
__global__ void vtrans_kernel(const __nv_bfloat16* __restrict__ V,
                              __nv_bfloat16* __restrict__ VT)
{
    __shared__ __nv_bfloat16 t[64][65];
    int bh = blockIdx.y, s0 = blockIdx.x * 64;
    int tid = threadIdx.x;
    for (int i = tid; i < 64*64; i += 256) {
        int r = i >> 6, c = i & 63;
        t[r][c] = V[((size_t)bh * SS + s0 + r) * DD + c];
    }
    __syncthreads();
    for (int i = tid; i < 64*64; i += 256) {
        int r = i >> 6, c = i & 63;
        VT[((size_t)bh * DD + r) * SS + s0 + c] = t[c][r];
    }
}

// ===========================================================================
// Projection GEMMs (cp.async 2-stage): MODE 0 QKV, MODE 1 out-proj.
// ===========================================================================
template<int MODE>
__global__ __launch_bounds__(256) void gemm_pipe_kernel(
    const __nv_bfloat16* __restrict__ Ah_, const __nv_bfloat16* __restrict__ Al_,
    const __nv_bfloat16* __restrict__ Bh_, const __nv_bfloat16* __restrict__ Bl_,
    const float* __restrict__ b0, const float* __restrict__ b1, const float* __restrict__ b2,
    float* __restrict__ outF,
    __nv_bfloat16* __restrict__ Oh_, __nv_bfloat16* __restrict__ Ol_)
{
    constexpr int NT = 32;
    extern __shared__ char sm[];
    const uint32_t sb = s2u(sm);
    const uint32_t aAH[2] = { sb,          sb + 10240 };
    const uint32_t aAL[2] = { sb + 20480,  sb + 30720 };
    const uint32_t aBH[2] = { sb + 40960,  sb + 51200 };
    const uint32_t aBL[2] = { sb + 61440,  sb + 71680 };

    const int tid = threadIdx.x, lane = tid & 31, wid = tid >> 5;
    const int wm = wid >> 2, wn = wid & 3;
    const size_t NX = (size_t)MT * DIM, NW = (size_t)DIM * DIM;

    const int z  = (MODE == 0) ? blockIdx.z : 0;
    const int n0 = blockIdx.x*128, m0 = blockIdx.y*128;

    const __nv_bfloat16* Abh = (MODE == 0 ? Ah_ + z*NX : Ah_) + (size_t)m0 * DIM;
    const __nv_bfloat16* Abl = (MODE == 0 ? Al_ + z*NX : Al_) + (size_t)m0 * DIM;
    const __nv_bfloat16* Bbh = (MODE == 0 ? Bh_ + z*NW : Bh_) + (size_t)n0 * DIM;
    const __nv_bfloat16* Bbl = (MODE == 0 ? Bl_ + z*NW : Bl_) + (size_t)n0 * DIM;
    const float* bias = (MODE == 0) ? (z == 0 ? b0 : (z == 1 ? b1 : b2)) : b0;

    float c[4][4][4] = {};

    auto load_stage = [&](int st, int k0){
        for (int idx = tid; idx < 512; idx += 256) {
            int r = idx >> 2, cc = idx & 3;
            uint32_t so = (uint32_t)r*80 + cc*16;
            size_t go = (size_t)r*DIM + k0 + cc*8;
            cpa16(aAH[st] + so, Abh + go);
            cpa16(aAL[st] + so, Abl + go);
            cpa16(aBH[st] + so, Bbh + go);
            cpa16(aBL[st] + so, Bbl + go);
        }
    };

    load_stage(0, 0);  CPA_COMMIT();
    load_stage(1, 32); CPA_COMMIT();

    for (int kt = 0; kt < NT; kt++) {
        if (kt + 1 < NT) { CPA_WAIT1(); } else { CPA_WAIT0(); }
        __syncthreads();
        const int st = kt & 1;
        tile_compute<4>(aAH[st], aAL[st], aBH[st], aBL[st], wm, wn, lane, c);
        __syncthreads();
        if (kt + 2 < NT) { load_stage(st, (kt + 2) * 32); CPA_COMMIT(); }
    }

    const int g = lane >> 2, tg = lane & 3;
#pragma unroll
    for (int mi = 0; mi < 4; mi++)
#pragma unroll
        for (int ni = 0; ni < 4; ni++) {
            const int m = m0 + wm*64 + mi*16 + g;
            const int n = n0 + wn*32 + ni*8 + tg*2;
            const float v00 = c[mi][ni][0], v01 = c[mi][ni][1];
            const float v10 = c[mi][ni][2], v11 = c[mi][ni][3];
            const float q0 = bias[n], q1 = bias[n+1];
            if (MODE == 1) {
                float2 r0 = { v00 + q0, v01 + q1 };
                float2 r1 = { v10 + q0, v11 + q1 };
                *(float2*)&outF[(size_t)m*DIM + n]     = r0;
                *(float2*)&outF[(size_t)(m+8)*DIM + n] = r1;
            } else {
                const int b = m >> 11, hd = n >> 6, d = n & 63;
                const size_t base = z*NX + (((size_t)(b*HH + hd))*SS + (m & 2047))*DD + d;
                __nv_bfloat16 h0,h1,h2,h3,l0,l1,l2,l3;
                bsplit(v00 + q0, h0, l0); bsplit(v01 + q1, h1, l1);
                bsplit(v10 + q0, h2, l2); bsplit(v11 + q1, h3, l3);
                *(uint32_t*)&Oh_[base]        = pk2(h0, h1);
                *(uint32_t*)&Ol_[base]        = pk2(l0, l1);
                *(uint32_t*)&Oh_[base + 8*DD] = pk2(h2, h3);
                *(uint32_t*)&Ol_[base + 8*DD] = pk2(l2, l3);
            }
        }
}

// ===========================================================================
// Logits fused: QK^T via cp.async 2-stage, epilogue applies scale+bias+mask
// from gmem, writes biased logits + per-stile partials. grid (16,16,32).
// ===========================================================================
__global__ __launch_bounds__(256) void logits_fused_kernel(
    const __nv_bfloat16* __restrict__ Qh, const __nv_bfloat16* __restrict__ Ql,
    const __nv_bfloat16* __restrict__ Kh, const __nv_bfloat16* __restrict__ Kl,
    const float* __restrict__ bias4d, const float* __restrict__ pad,
    float* __restrict__ attn, float2* __restrict__ part)
{
    extern __shared__ char sm[];
    const uint32_t sb = s2u(sm);
    const uint32_t aAH[2] = { sb,          sb + 10240 };
    const uint32_t aAL[2] = { sb + 20480,  sb + 30720 };
    const uint32_t aBH[2] = { sb + 40960,  sb + 51200 };
    const uint32_t aBL[2] = { sb + 61440,  sb + 71680 };

    const int tid = threadIdx.x, lane = tid & 31, wid = tid >> 5;
    const int wm = wid >> 2, wn = wid & 3;
    const int bh = blockIdx.z, b = bh >> 4;
    const int stile = blockIdx.x;
    const int n0 = stile*128, m0 = blockIdx.y*128;

    const __nv_bfloat16* Abh = Qh + ((size_t)bh*SS + m0) * DD;
    const __nv_bfloat16* Abl = Ql + ((size_t)bh*SS + m0) * DD;
    const __nv_bfloat16* Bbh = Kh + ((size_t)bh*SS + n0) * DD;
    const __nv_bfloat16* Bbl = Kl + ((size_t)bh*SS + n0) * DD;

    auto load_stage = [&](int st, int k0){
        for (int idx = tid; idx < 512; idx += 256) {
            int r = idx >> 2, cc = idx & 3;
            uint32_t so = (uint32_t)r*80 + cc*16;
            size_t go = (size_t)r*DD + k0 + cc*8;
            cpa16(aAH[st] + so, Abh + go);
            cpa16(aAL[st] + so, Abl + go);
            cpa16(aBH[st] + so, Bbh + go);
            cpa16(aBL[st] + so, Bbl + go);
        }
    };

    load_stage(0, 0);  CPA_COMMIT();
    load_stage(1, 32); CPA_COMMIT();

    float c[4][4][4] = {};
    CPA_WAIT1();
    __syncthreads();
    tile_compute<4>(aAH[0], aAL[0], aBH[0], aBL[0], wm, wn, lane, c);
    CPA_WAIT0();
    __syncthreads();
    tile_compute<4>(aAH[1], aAL[1], aBH[1], aBL[1], wm, wn, lane, c);
    __syncthreads();

    // epilogue: bias+mask from gmem, write logits, partial (max,sumexp)
    float2* spair = (float2*)sm;   // reuse data smem: [4][128]
    const int g = lane >> 2, tg = lane & 3;

#pragma unroll
    for (int mi = 0; mi < 4; mi++)
#pragma unroll
        for (int half = 0; half < 2; half++) {
            const int rloc = wm*64 + mi*16 + half*8 + g;
            const int t = m0 + rloc;
            const float mt = 1.0f - pad[b*SS + t];
            const float* bp = &bias4d[((size_t)bh*SS + t)*SS + n0];
            float* ap = &attn[((size_t)bh*SS + t)*SS + n0];
            float vv[8];
#pragma unroll
            for (int ni = 0; ni < 4; ni++) {
                const int nl = wn*32 + ni*8 + tg*2;
                const float ms0 = 1.0f - pad[b*SS + n0 + nl];
                const float ms1 = 1.0f - pad[b*SS + n0 + nl + 1];
                float x0 = c[mi][ni][half*2+0]*0.125f + bp[nl]   - 1e9f*(1.0f - mt*ms0);
                float x1 = c[mi][ni][half*2+1]*0.125f + bp[nl+1] - 1e9f*(1.0f - mt*ms1);
                vv[ni*2]   = x0;
                vv[ni*2+1] = x1;
                float2 w = { x0, x1 };
                *(float2*)&ap[nl] = w;
            }
            float mx = vv[0];
#pragma unroll
            for (int j = 1; j < 8; j++) mx = fmaxf(mx, vv[j]);
            mx = fmaxf(mx, __shfl_xor_sync(~0u, mx, 1));
            mx = fmaxf(mx, __shfl_xor_sync(~0u, mx, 2));
            float se = 0.f;
#pragma unroll
            for (int j = 0; j < 8; j++) se += __expf(vv[j] - mx);
            se += __shfl_xor_sync(~0u, se, 1);
            se += __shfl_xor_sync(~0u, se, 2);
            if (tg == 0) spair[wn*128 + rloc] = make_float2(mx, se);
        }
    __syncthreads();

    if (tid < 128) {
        float2 p0 = spair[tid], p1 = spair[128 + tid];
        float2 p2 = spair[256 + tid], p3 = spair[384 + tid];
        float m01 = fmaxf(p0.x, p1.x), m23 = fmaxf(p2.x, p3.x);
        float m = fmaxf(m01, m23);
        float s = p0.y*__expf(p0.x - m) + p1.y*__expf(p1.x - m)
                + p2.y*__expf(p2.x - m) + p3.y*__expf(p3.x - m);
        part[(((size_t)bh*SS) + m0 + tid)*16 + stile] = make_float2(m, s);
    }
}

// ---- merge 16 partials per row -> (max, 1/sum) ----
__global__ void ms_reduce_kernel(const float2* __restrict__ part,
                                 float2* __restrict__ ms)
{
    const int row = blockIdx.x * 256 + threadIdx.x;
    const float2* p = part + (size_t)row * 16;
    float2 v[16];
#pragma unroll
    for (int i = 0; i < 8; i++) {
        float4 a = *(const float4*)&p[i*2];
        v[i*2]   = make_float2(a.x, a.y);
        v[i*2+1] = make_float2(a.z, a.w);
    }
    float m = v[0].x;
#pragma unroll
    for (int i = 1; i < 16; i++) m = fmaxf(m, v[i].x);
    float s = 0.f;
#pragma unroll
    for (int i = 0; i < 16; i++) s += v[i].y * __expf(v[i].x - m);
    ms[row] = make_float2(m, 1.0f / s);
}

// ===========================================================================
// AV fused: merge-free (reads precomputed ms); normalize + write weights +
// split to bf16 + MMA with VT. grid (16,32). dyn 78848.
// ===========================================================================
__global__ __launch_bounds__(256) void av_pipe_kernel(
    float* __restrict__ attn,
    const float2* __restrict__ ms,
    const __nv_bfloat16* __restrict__ VTh, const __nv_bfloat16* __restrict__ VTl,
    __nv_bfloat16* __restrict__ Ch, __nv_bfloat16* __restrict__ Cl)
{
    extern __shared__ char sm[];
    const uint32_t sb = s2u(sm);
    const uint32_t aAF[2] = { sb, sb + 18432 };
    const uint32_t aAH = sb + 36864, aAL = sb + 47104;
    const uint32_t aBH[2] = { sb + 57344, sb + 62464 };
    const uint32_t aBL[2] = { sb + 67584, sb + 72704 };
    float2* sms = (float2*)(sm + 77824);

    const int tid = threadIdx.x, lane = tid & 31, wid = tid >> 5;
    const int wm = wid >> 2, wn = wid & 3;
    const int bh = blockIdx.y, b = bh >> 4, hd = bh & 15;
    const int m0 = blockIdx.x * 128;

    float* Abf = attn + ((size_t)bh*SS + m0) * SS;
    const __nv_bfloat16* Bbh = VTh + (size_t)bh*DD*SS;
    const __nv_bfloat16* Bbl = VTl + (size_t)bh*DD*SS;

    if (tid < 128) sms[tid] = ms[(size_t)bh*SS + m0 + tid];

    float c[4][2][4] = {};

    auto load_stage = [&](int st, int k0){
        for (int idx = tid; idx < 1024; idx += 256) {
            int r = idx >> 3, cc = idx & 7;
            cpa16(aAF[st] + (uint32_t)r*144 + cc*16, Abf + (size_t)r*SS + k0 + cc*4);
        }
        for (int idx = tid; idx < 256; idx += 256) {
            int r = idx >> 2, cc = idx & 3;
            uint32_t so = (uint32_t)r*80 + cc*16;
            size_t go = (size_t)r*SS + k0 + cc*8;
            cpa16(aBH[st] + so, Bbh + go);
            cpa16(aBL[st] + so, Bbl + go);
        }
    };

    load_stage(0, 0);  CPA_COMMIT();
    load_stage(1, 32); CPA_COMMIT();

    for (int kt = 0; kt < 64; kt++) {
        if (kt + 1 < 64) { CPA_WAIT1(); } else { CPA_WAIT0(); }
        __syncthreads();
        const int st = kt & 1;
        const int k0 = kt * 32;
        for (int idx = tid; idx < 1024; idx += 256) {
            int r = idx >> 3, cc = idx & 7;
            float4 w = *(const float4*)(sm + st*18432 + r*144 + cc*16);
            float2 q = sms[r];
            w.x = __expf(w.x - q.x) * q.y;
            w.y = __expf(w.y - q.x) * q.y;
            w.z = __expf(w.z - q.x) * q.y;
            w.w = __expf(w.w - q.x) * q.y;
            *(float4*)&Abf[(size_t)r*SS + k0 + cc*4] = w;
            __nv_bfloat16 h0,h1,h2,h3,l0,l1,l2,l3;
            bsplit(w.x,h0,l0); bsplit(w.y,h1,l1); bsplit(w.z,h2,l2); bsplit(w.w,h3,l3);
            uint2 hp = { pk2(h0,h1), pk2(h2,h3) };
            uint2 lp = { pk2(l0,l1), pk2(l2,l3) };
            *(uint2*)(sm + 36864 + r*80 + cc*8) = hp;
            *(uint2*)(sm + 47104 + r*80 + cc*8) = lp;
        }
        __syncthreads();
        tile_compute<2>(aAH, aAL, aBH[st], aBL[st], wm, wn, lane, c);
        __syncthreads();
        if (kt + 2 < 64) { load_stage(st, (kt + 2) * 32); CPA_COMMIT(); }
    }

    const int g = lane >> 2, tg = lane & 3;
#pragma unroll
    for (int mi = 0; mi < 4; mi++)
#pragma unroll
        for (int ni = 0; ni < 2; ni++) {
            const int m = m0 + wm*64 + mi*16 + g;
            const int n = wn*16 + ni*8 + tg*2;
            const size_t base = ((size_t)(b*SS + m))*DIM + hd*DD + n;
            __nv_bfloat16 h0,h1,h2,h3,l0,l1,l2,l3;
            bsplit(c[mi][ni][0], h0, l0); bsplit(c[mi][ni][1], h1, l1);
            bsplit(c[mi][ni][2], h2, l2); bsplit(c[mi][ni][3], h3, l3);
            *(uint32_t*)&Ch[base]         = pk2(h0, h1);
            *(uint32_t*)&Cl[base]         = pk2(l0, l1);
            *(uint32_t*)&Ch[base + 8*DIM] = pk2(h2, h3);
            *(uint32_t*)&Cl[base + 8*DIM] = pk2(l2, l3);
        }
}

// ---------------------------------------------------------------------------
extern "C" void kernel_launch(void* const* d_in, const int* in_sizes, int n_in,
                              void* d_out, int out_size)
{
    const float* xin[3] = { (const float*)d_in[0], (const float*)d_in[1], (const float*)d_in[2] };
    const float* attnbias = (const float*)d_in[3];
    const float* paddings = (const float*)d_in[4];
    const float* ww[4] = { (const float*)d_in[5], (const float*)d_in[7],
                           (const float*)d_in[9], (const float*)d_in[11] };
    const float* wb[4] = { (const float*)d_in[6], (const float*)d_in[8],
                           (const float*)d_in[10], (const float*)d_in[12] };

    float* out  = (float*)d_out;
    float* attn = out + (size_t)MT * DIM;

    __nv_bfloat16 *xh, *xl, *twh, *twl, *ph, *pl, *vth, *vtl, *ch, *cl;
    float2 *partp, *msp;
    cudaGetSymbolAddress((void**)&xh, g_xh);   cudaGetSymbolAddress((void**)&xl, g_xl);
    cudaGetSymbolAddress((void**)&twh, g_twh); cudaGetSymbolAddress((void**)&twl, g_twl);
    cudaGetSymbolAddress((void**)&ph, g_ph);   cudaGetSymbolAddress((void**)&pl, g_pl);
    cudaGetSymbolAddress((void**)&vth, g_vth); cudaGetSymbolAddress((void**)&vtl, g_vtl);
    cudaGetSymbolAddress((void**)&ch, g_ch);   cudaGetSymbolAddress((void**)&cl, g_cl);
    cudaGetSymbolAddress((void**)&partp, g_part); cudaGetSymbolAddress((void**)&msp, g_ms);

    static int attr_done = 0;
    if (!attr_done) {
        cudaFuncSetAttribute(gemm_pipe_kernel<0>,  cudaFuncAttributeMaxDynamicSharedMemorySize, 81920);
        cudaFuncSetAttribute(gemm_pipe_kernel<1>,  cudaFuncAttributeMaxDynamicSharedMemorySize, 81920);
        cudaFuncSetAttribute(logits_fused_kernel,  cudaFuncAttributeMaxDynamicSharedMemorySize, 81920);
        cudaFuncSetAttribute(av_pipe_kernel,       cudaFuncAttributeMaxDynamicSharedMemorySize, 78848);
        attr_done = 1;
    }

    const size_t NX = (size_t)MT * DIM;
    const size_t NW = (size_t)DIM * DIM;

    for (int i = 0; i < 3; i++)
        split_kernel<<<NX/1024, 256>>>(xin[i], xh + i*NX, xl + i*NX);
    for (int i = 0; i < 4; i++)
        wtrans_kernel<<<dim3(32,32), dim3(32,8)>>>(ww[i], twh + i*NW, twl + i*NW);

    // QKV projections, batched
    gemm_pipe_kernel<0><<<dim3(8,32,3), 256, 81920>>>(
        xh, xl, twh, twl, wb[0], wb[1], wb[2], nullptr, ph, pl);

    __nv_bfloat16 *qh = ph, *ql = pl;
    __nv_bfloat16 *kh = ph + NX, *kl = pl + NX;
    __nv_bfloat16 *vh = ph + 2*NX, *vl = pl + 2*NX;

    vtrans_kernel<<<dim3(32, NBH), 256>>>(vh, vth);
    vtrans_kernel<<<dim3(32, NBH), 256>>>(vl, vtl);

    // logits + bias + mask + softmax partials
    logits_fused_kernel<<<dim3(16,16,NBH), 256, 81920>>>(
        qh, ql, kh, kl, attnbias, paddings, attn, partp);

    // merge partials -> (max, 1/sum) per row
    ms_reduce_kernel<<<(NBH*SS)/256, 256>>>(partp, msp);

    // AV: normalize + write weights + MMA
    av_pipe_kernel<<<dim3(16, NBH), 256, 78848>>>(attn, msp, vth, vtl, ch, cl);

    // output projection -> fp32 out
    gemm_pipe_kernel<1><<<dim3(8,32), 256, 81920>>>(
        ch, cl, twh + 3*NW, twl + 3*NW, wb[3], nullptr, nullptr, out, nullptr, nullptr);
}

// round 15
// speedup vs baseline: 1.3401x; 1.0883x over previous
#include <cuda_runtime.h>
#include <cuda_bf16.h>
#include <stdint.h>

#define BB  2
#define SS  2048
#define DIM 1024
#define HH  16
#define DD  64
#define MT  (BB*SS)
#define NBH (BB*HH)

// ---- device scratch ----
__device__ __nv_bfloat16 g_xh[3][MT*DIM], g_xl[3][MT*DIM];
__device__ __nv_bfloat16 g_twh[4][DIM*DIM], g_twl[4][DIM*DIM];
__device__ __nv_bfloat16 g_ph[3][NBH*SS*DD], g_pl[3][NBH*SS*DD];
__device__ __nv_bfloat16 g_vth[NBH*DD*SS], g_vtl[NBH*DD*SS];
__device__ __nv_bfloat16 g_ch[MT*DIM], g_cl[MT*DIM];
__device__ float2 g_part[(size_t)NBH*SS*16];
__device__ float2 g_ms[(size_t)NBH*SS];

#define STRD 40

// ---- helpers ----
__device__ __forceinline__ uint32_t s2u(const void* p){
    uint32_t a;
    asm("{ .reg .u64 t; cvta.to.shared.u64 t, %1; cvt.u32.u64 %0, t; }":"=r"(a):"l"(p));
    return a;
}
__device__ __forceinline__ void bsplit(float v, __nv_bfloat16& h, __nv_bfloat16& l){
    h = __float2bfloat16(v);
    l = __float2bfloat16(v - __bfloat162float(h));
}
__device__ __forceinline__ uint32_t pk2(__nv_bfloat16 a, __nv_bfloat16 b){
    __nv_bfloat162 t(a, b); return *(uint32_t*)&t;
}
__device__ __forceinline__ void ldmx4(uint32_t* r, uint32_t addr){
    asm volatile("ldmatrix.sync.aligned.m8n8.x4.shared.b16 {%0,%1,%2,%3}, [%4];"
        : "=r"(r[0]),"=r"(r[1]),"=r"(r[2]),"=r"(r[3]) : "r"(addr));
}
__device__ __forceinline__ void ldmx2(uint32_t* r, uint32_t addr){
    asm volatile("ldmatrix.sync.aligned.m8n8.x2.shared.b16 {%0,%1}, [%2];"
        : "=r"(r[0]),"=r"(r[1]) : "r"(addr));
}
__device__ __forceinline__ void mma16816(float* c, const uint32_t* a, const uint32_t* b){
    asm volatile("mma.sync.aligned.m16n8k16.row.col.f32.bf16.bf16.f32 "
        "{%0,%1,%2,%3}, {%4,%5,%6,%7}, {%8,%9}, {%0,%1,%2,%3};"
        : "+f"(c[0]),"+f"(c[1]),"+f"(c[2]),"+f"(c[3])
        : "r"(a[0]),"r"(a[1]),"r"(a[2]),"r"(a[3]), "r"(b[0]),"r"(b[1]));
}
__device__ __forceinline__ void cpa16(uint32_t s, const void* g){
    asm volatile("cp.async.cg.shared.global [%0], [%1], 16;" :: "r"(s), "l"(g));
}
#define CPA_COMMIT() asm volatile("cp.async.commit_group;" ::: "memory")
#define CPA_WAIT1()  asm volatile("cp.async.wait_group 1;" ::: "memory")
#define CPA_WAIT0()  asm volatile("cp.async.wait_group 0;" ::: "memory")

// ---- warp-tile compute ----
// Product index p outermost: consecutive MMAs hit DIFFERENT accumulators
// (16-deep ILP) instead of chaining 3 dependent MMAs on one accumulator.
// Per-accumulator order stays hh -> hl -> lh: bit-identical numerics.
template<int WNT>
__device__ __forceinline__ void tile_compute(
    uint32_t aAh, uint32_t aAl, uint32_t aBh, uint32_t aBl,
    int wm, int wn, int lane, float c[4][WNT][4])
{
#pragma unroll
    for (int h = 0; h < 2; h++) {
        uint32_t fAh[4][4], fAl[4][4], fBh[WNT][2], fBl[WNT][2];
        const int ar = wm*64 + (lane & 15);
        const int ac = h*16 + ((lane >> 4) << 3);
#pragma unroll
        for (int mi = 0; mi < 4; mi++) {
            uint32_t off = (uint32_t)((ar + mi*16)*STRD + ac) * 2;
            ldmx4(fAh[mi], aAh + off);
            ldmx4(fAl[mi], aAl + off);
        }
        const int br = wn*(WNT*8) + (lane & 7);
        const int bc = h*16 + ((lane >> 3) & 1)*8;
#pragma unroll
        for (int ni = 0; ni < WNT; ni++) {
            uint32_t off = (uint32_t)((br + ni*8)*STRD + bc) * 2;
            ldmx2(fBh[ni], aBh + off);
            ldmx2(fBl[ni], aBl + off);
        }
#pragma unroll
        for (int p = 0; p < 3; p++)
#pragma unroll
            for (int mi = 0; mi < 4; mi++)
#pragma unroll
                for (int ni = 0; ni < WNT; ni++)
                    mma16816(c[mi][ni],
                             (p == 2) ? fAl[mi] : fAh[mi],
                             (p == 1) ? fBl[ni] : fBh[ni]);
    }
}

// ---- fp32 -> bf16 hi/lo split ----
__global__ void split_kernel(const float* __restrict__ x,
                             __nv_bfloat16* __restrict__ h,
                             __nv_bfloat16* __restrict__ l)
{
    int i = (blockIdx.x * blockDim.x + threadIdx.x) * 4;
    float4 v = *(const float4*)&x[i];
    __nv_bfloat16 h0,h1,h2,h3,l0,l1,l2,l3;
    bsplit(v.x,h0,l0); bsplit(v.y,h1,l1); bsplit(v.z,h2,l2); bsplit(v.w,h3,l3);
    uint2 hp = { pk2(h0,h1), pk2(h2,h3) };
    uint2 lp = { pk2(l0,l1), pk2(l2,l3) };
    *(uint2*)&h[i] = hp; *(uint2*)&l[i] = lp;
}

// ---- W[K,N] -> WT[N,K] hi/lo ----
__global__ void wtrans_kernel(const float* __restrict__ W,
                              __nv_bfloat16* __restrict__ Th,
                              __nv_bfloat16* __restrict__ Tl)
{
    __shared__ float t[32][33];
    int bx = blockIdx.x * 32, by = blockIdx.y * 32;
    int x = threadIdx.x, y = threadIdx.y;
    for (int yy = y; yy < 32; yy += 8)
        t[yy][x] = W[(size_t)(by + yy) * DIM + bx + x];
    __syncthreads();
    for (int yy = y; yy < 32; yy += 8) {
        __nv_bfloat16 h, l; bsplit(t[x][yy], h, l);
        Th[(size_t)(bx + yy) * DIM + by + x] = h;
        Tl[(size_t)(bx + yy) * DIM + by + x] = l;
    }
}

// ---- V [bh,s,d] -> VT [bh,d,s] (bf16) ----
__global__ void vtrans_kernel(const __nv_bfloat16* __restrict__ V,
                              __nv_bfloat16* __restrict__ VT)
{
    __shared__ __nv_bfloat16 t[64][65];
    int bh = blockIdx.y, s0 = blockIdx.x * 64;
    int tid = threadIdx.x;
    for (int i = tid; i < 64*64; i += 256) {
        int r = i >> 6, c = i & 63;
        t[r][c] = V[((size_t)bh * SS + s0 + r) * DD + c];
    }
    __syncthreads();
    for (int i = tid; i < 64*64; i += 256) {
        int r = i >> 6, c = i & 63;
        VT[((size_t)bh * DD + r) * SS + s0 + c] = t[c][r];
    }
}

// ===========================================================================
// Projection GEMMs (cp.async 2-stage): MODE 0 QKV, MODE 1 out-proj.
// ===========================================================================
template<int MODE>
__global__ __launch_bounds__(256) void gemm_pipe_kernel(
    const __nv_bfloat16* __restrict__ Ah_, const __nv_bfloat16* __restrict__ Al_,
    const __nv_bfloat16* __restrict__ Bh_, const __nv_bfloat16* __restrict__ Bl_,
    const float* __restrict__ b0, const float* __restrict__ b1, const float* __restrict__ b2,
    float* __restrict__ outF,
    __nv_bfloat16* __restrict__ Oh_, __nv_bfloat16* __restrict__ Ol_)
{
    constexpr int NT = 32;
    extern __shared__ char sm[];
    const uint32_t sb = s2u(sm);
    const uint32_t aAH[2] = { sb,          sb + 10240 };
    const uint32_t aAL[2] = { sb + 20480,  sb + 30720 };
    const uint32_t aBH[2] = { sb + 40960,  sb + 51200 };
    const uint32_t aBL[2] = { sb + 61440,  sb + 71680 };

    const int tid = threadIdx.x, lane = tid & 31, wid = tid >> 5;
    const int wm = wid >> 2, wn = wid & 3;
    const size_t NX = (size_t)MT * DIM, NW = (size_t)DIM * DIM;

    const int z  = (MODE == 0) ? blockIdx.z : 0;
    const int n0 = blockIdx.x*128, m0 = blockIdx.y*128;

    const __nv_bfloat16* Abh = (MODE == 0 ? Ah_ + z*NX : Ah_) + (size_t)m0 * DIM;
    const __nv_bfloat16* Abl = (MODE == 0 ? Al_ + z*NX : Al_) + (size_t)m0 * DIM;
    const __nv_bfloat16* Bbh = (MODE == 0 ? Bh_ + z*NW : Bh_) + (size_t)n0 * DIM;
    const __nv_bfloat16* Bbl = (MODE == 0 ? Bl_ + z*NW : Bl_) + (size_t)n0 * DIM;
    const float* bias = (MODE == 0) ? (z == 0 ? b0 : (z == 1 ? b1 : b2)) : b0;

    float c[4][4][4] = {};

    auto load_stage = [&](int st, int k0){
        for (int idx = tid; idx < 512; idx += 256) {
            int r = idx >> 2, cc = idx & 3;
            uint32_t so = (uint32_t)r*80 + cc*16;
            size_t go = (size_t)r*DIM + k0 + cc*8;
            cpa16(aAH[st] + so, Abh + go);
            cpa16(aAL[st] + so, Abl + go);
            cpa16(aBH[st] + so, Bbh + go);
            cpa16(aBL[st] + so, Bbl + go);
        }
    };

    load_stage(0, 0);  CPA_COMMIT();
    load_stage(1, 32); CPA_COMMIT();

    for (int kt = 0; kt < NT; kt++) {
        if (kt + 1 < NT) { CPA_WAIT1(); } else { CPA_WAIT0(); }
        __syncthreads();
        const int st = kt & 1;
        tile_compute<4>(aAH[st], aAL[st], aBH[st], aBL[st], wm, wn, lane, c);
        __syncthreads();
        if (kt + 2 < NT) { load_stage(st, (kt + 2) * 32); CPA_COMMIT(); }
    }

    const int g = lane >> 2, tg = lane & 3;
#pragma unroll
    for (int mi = 0; mi < 4; mi++)
#pragma unroll
        for (int ni = 0; ni < 4; ni++) {
            const int m = m0 + wm*64 + mi*16 + g;
            const int n = n0 + wn*32 + ni*8 + tg*2;
            const float v00 = c[mi][ni][0], v01 = c[mi][ni][1];
            const float v10 = c[mi][ni][2], v11 = c[mi][ni][3];
            const float q0 = bias[n], q1 = bias[n+1];
            if (MODE == 1) {
                float2 r0 = { v00 + q0, v01 + q1 };
                float2 r1 = { v10 + q0, v11 + q1 };
                *(float2*)&outF[(size_t)m*DIM + n]     = r0;
                *(float2*)&outF[(size_t)(m+8)*DIM + n] = r1;
            } else {
                const int b = m >> 11, hd = n >> 6, d = n & 63;
                const size_t base = z*NX + (((size_t)(b*HH + hd))*SS + (m & 2047))*DD + d;
                __nv_bfloat16 h0,h1,h2,h3,l0,l1,l2,l3;
                bsplit(v00 + q0, h0, l0); bsplit(v01 + q1, h1, l1);
                bsplit(v10 + q0, h2, l2); bsplit(v11 + q1, h3, l3);
                *(uint32_t*)&Oh_[base]        = pk2(h0, h1);
                *(uint32_t*)&Ol_[base]        = pk2(l0, l1);
                *(uint32_t*)&Oh_[base + 8*DD] = pk2(h2, h3);
                *(uint32_t*)&Ol_[base + 8*DD] = pk2(l2, l3);
            }
        }
}

// ===========================================================================
// Logits fused: QK^T via cp.async 2-stage, epilogue applies scale+bias+mask
// from gmem, writes biased logits + per-stile partials. grid (16,16,32).
// ===========================================================================
__global__ __launch_bounds__(256) void logits_fused_kernel(
    const __nv_bfloat16* __restrict__ Qh, const __nv_bfloat16* __restrict__ Ql,
    const __nv_bfloat16* __restrict__ Kh, const __nv_bfloat16* __restrict__ Kl,
    const float* __restrict__ bias4d, const float* __restrict__ pad,
    float* __restrict__ attn, float2* __restrict__ part)
{
    extern __shared__ char sm[];
    const uint32_t sb = s2u(sm);
    const uint32_t aAH[2] = { sb,          sb + 10240 };
    const uint32_t aAL[2] = { sb + 20480,  sb + 30720 };
    const uint32_t aBH[2] = { sb + 40960,  sb + 51200 };
    const uint32_t aBL[2] = { sb + 61440,  sb + 71680 };

    const int tid = threadIdx.x, lane = tid & 31, wid = tid >> 5;
    const int wm = wid >> 2, wn = wid & 3;
    const int bh = blockIdx.z, b = bh >> 4;
    const int stile = blockIdx.x;
    const int n0 = stile*128, m0 = blockIdx.y*128;

    const __nv_bfloat16* Abh = Qh + ((size_t)bh*SS + m0) * DD;
    const __nv_bfloat16* Abl = Ql + ((size_t)bh*SS + m0) * DD;
    const __nv_bfloat16* Bbh = Kh + ((size_t)bh*SS + n0) * DD;
    const __nv_bfloat16* Bbl = Kl + ((size_t)bh*SS + n0) * DD;

    auto load_stage = [&](int st, int k0){
        for (int idx = tid; idx < 512; idx += 256) {
            int r = idx >> 2, cc = idx & 3;
            uint32_t so = (uint32_t)r*80 + cc*16;
            size_t go = (size_t)r*DD + k0 + cc*8;
            cpa16(aAH[st] + so, Abh + go);
            cpa16(aAL[st] + so, Abl + go);
            cpa16(aBH[st] + so, Bbh + go);
            cpa16(aBL[st] + so, Bbl + go);
        }
    };

    load_stage(0, 0);  CPA_COMMIT();
    load_stage(1, 32); CPA_COMMIT();

    float c[4][4][4] = {};
    CPA_WAIT1();
    __syncthreads();
    tile_compute<4>(aAH[0], aAL[0], aBH[0], aBL[0], wm, wn, lane, c);
    CPA_WAIT0();
    __syncthreads();
    tile_compute<4>(aAH[1], aAL[1], aBH[1], aBL[1], wm, wn, lane, c);
    __syncthreads();

    // epilogue: bias+mask from gmem, write logits, partial (max,sumexp)
    float2* spair = (float2*)sm;   // reuse data smem: [4][128]
    const int g = lane >> 2, tg = lane & 3;

#pragma unroll
    for (int mi = 0; mi < 4; mi++)
#pragma unroll
        for (int half = 0; half < 2; half++) {
            const int rloc = wm*64 + mi*16 + half*8 + g;
            const int t = m0 + rloc;
            const float mt = 1.0f - pad[b*SS + t];
            const float* bp = &bias4d[((size_t)bh*SS + t)*SS + n0];
            float* ap = &attn[((size_t)bh*SS + t)*SS + n0];
            float vv[8];
#pragma unroll
            for (int ni = 0; ni < 4; ni++) {
                const int nl = wn*32 + ni*8 + tg*2;
                const float ms0 = 1.0f - pad[b*SS + n0 + nl];
                const float ms1 = 1.0f - pad[b*SS + n0 + nl + 1];
                float x0 = c[mi][ni][half*2+0]*0.125f + bp[nl]   - 1e9f*(1.0f - mt*ms0);
                float x1 = c[mi][ni][half*2+1]*0.125f + bp[nl+1] - 1e9f*(1.0f - mt*ms1);
                vv[ni*2]   = x0;
                vv[ni*2+1] = x1;
                float2 w = { x0, x1 };
                *(float2*)&ap[nl] = w;
            }
            float mx = vv[0];
#pragma unroll
            for (int j = 1; j < 8; j++) mx = fmaxf(mx, vv[j]);
            mx = fmaxf(mx, __shfl_xor_sync(~0u, mx, 1));
            mx = fmaxf(mx, __shfl_xor_sync(~0u, mx, 2));
            float se = 0.f;
#pragma unroll
            for (int j = 0; j < 8; j++) se += __expf(vv[j] - mx);
            se += __shfl_xor_sync(~0u, se, 1);
            se += __shfl_xor_sync(~0u, se, 2);
            if (tg == 0) spair[wn*128 + rloc] = make_float2(mx, se);
        }
    __syncthreads();

    if (tid < 128) {
        float2 p0 = spair[tid], p1 = spair[128 + tid];
        float2 p2 = spair[256 + tid], p3 = spair[384 + tid];
        float m01 = fmaxf(p0.x, p1.x), m23 = fmaxf(p2.x, p3.x);
        float m = fmaxf(m01, m23);
        float s = p0.y*__expf(p0.x - m) + p1.y*__expf(p1.x - m)
                + p2.y*__expf(p2.x - m) + p3.y*__expf(p3.x - m);
        part[(((size_t)bh*SS) + m0 + tid)*16 + stile] = make_float2(m, s);
    }
}

// ---- merge 16 partials per row -> (max, 1/sum) ----
__global__ void ms_reduce_kernel(const float2* __restrict__ part,
                                 float2* __restrict__ ms)
{
    const int row = blockIdx.x * 256 + threadIdx.x;
    const float2* p = part + (size_t)row * 16;
    float2 v[16];
#pragma unroll
    for (int i = 0; i < 8; i++) {
        float4 a = *(const float4*)&p[i*2];
        v[i*2]   = make_float2(a.x, a.y);
        v[i*2+1] = make_float2(a.z, a.w);
    }
    float m = v[0].x;
#pragma unroll
    for (int i = 1; i < 16; i++) m = fmaxf(m, v[i].x);
    float s = 0.f;
#pragma unroll
    for (int i = 0; i < 16; i++) s += v[i].y * __expf(v[i].x - m);
    ms[row] = make_float2(m, 1.0f / s);
}

// ===========================================================================
// AV fused: normalize + write weights + split + MMA. grid (16,32). dyn 78848.
// ===========================================================================
__global__ __launch_bounds__(256) void av_pipe_kernel(
    float* __restrict__ attn,
    const float2* __restrict__ ms,
    const __nv_bfloat16* __restrict__ VTh, const __nv_bfloat16* __restrict__ VTl,
    __nv_bfloat16* __restrict__ Ch, __nv_bfloat16* __restrict__ Cl)
{
    extern __shared__ char sm[];
    const uint32_t sb = s2u(sm);
    const uint32_t aAF[2] = { sb, sb + 18432 };
    const uint32_t aAH = sb + 36864, aAL = sb + 47104;
    const uint32_t aBH[2] = { sb + 57344, sb + 62464 };
    const uint32_t aBL[2] = { sb + 67584, sb + 72704 };
    float2* sms = (float2*)(sm + 77824);

    const int tid = threadIdx.x, lane = tid & 31, wid = tid >> 5;
    const int wm = wid >> 2, wn = wid & 3;
    const int bh = blockIdx.y, b = bh >> 4, hd = bh & 15;
    const int m0 = blockIdx.x * 128;

    float* Abf = attn + ((size_t)bh*SS + m0) * SS;
    const __nv_bfloat16* Bbh = VTh + (size_t)bh*DD*SS;
    const __nv_bfloat16* Bbl = VTl + (size_t)bh*DD*SS;

    if (tid < 128) sms[tid] = ms[(size_t)bh*SS + m0 + tid];

    float c[4][2][4] = {};

    auto load_stage = [&](int st, int k0){
        for (int idx = tid; idx < 1024; idx += 256) {
            int r = idx >> 3, cc = idx & 7;
            cpa16(aAF[st] + (uint32_t)r*144 + cc*16, Abf + (size_t)r*SS + k0 + cc*4);
        }
        for (int idx = tid; idx < 256; idx += 256) {
            int r = idx >> 2, cc = idx & 3;
            uint32_t so = (uint32_t)r*80 + cc*16;
            size_t go = (size_t)r*SS + k0 + cc*8;
            cpa16(aBH[st] + so, Bbh + go);
            cpa16(aBL[st] + so, Bbl + go);
        }
    };

    load_stage(0, 0);  CPA_COMMIT();
    load_stage(1, 32); CPA_COMMIT();

    for (int kt = 0; kt < 64; kt++) {
        if (kt + 1 < 64) { CPA_WAIT1(); } else { CPA_WAIT0(); }
        __syncthreads();
        const int st = kt & 1;
        const int k0 = kt * 32;
        for (int idx = tid; idx < 1024; idx += 256) {
            int r = idx >> 3, cc = idx & 7;
            float4 w = *(const float4*)(sm + st*18432 + r*144 + cc*16);
            float2 q = sms[r];
            w.x = __expf(w.x - q.x) * q.y;
            w.y = __expf(w.y - q.x) * q.y;
            w.z = __expf(w.z - q.x) * q.y;
            w.w = __expf(w.w - q.x) * q.y;
            *(float4*)&Abf[(size_t)r*SS + k0 + cc*4] = w;
            __nv_bfloat16 h0,h1,h2,h3,l0,l1,l2,l3;
            bsplit(w.x,h0,l0); bsplit(w.y,h1,l1); bsplit(w.z,h2,l2); bsplit(w.w,h3,l3);
            uint2 hp = { pk2(h0,h1), pk2(h2,h3) };
            uint2 lp = { pk2(l0,l1), pk2(l2,l3) };
            *(uint2*)(sm + 36864 + r*80 + cc*8) = hp;
            *(uint2*)(sm + 47104 + r*80 + cc*8) = lp;
        }
        __syncthreads();
        tile_compute<2>(aAH, aAL, aBH[st], aBL[st], wm, wn, lane, c);
        __syncthreads();
        if (kt + 2 < 64) { load_stage(st, (kt + 2) * 32); CPA_COMMIT(); }
    }

    const int g = lane >> 2, tg = lane & 3;
#pragma unroll
    for (int mi = 0; mi < 4; mi++)
#pragma unroll
        for (int ni = 0; ni < 2; ni++) {
            const int m = m0 + wm*64 + mi*16 + g;
            const int n = wn*16 + ni*8 + tg*2;
            const size_t base = ((size_t)(b*SS + m))*DIM + hd*DD + n;
            __nv_bfloat16 h0,h1,h2,h3,l0,l1,l2,l3;
            bsplit(c[mi][ni][0], h0, l0); bsplit(c[mi][ni][1], h1, l1);
            bsplit(c[mi][ni][2], h2, l2); bsplit(c[mi][ni][3], h3, l3);
            *(uint32_t*)&Ch[base]         = pk2(h0, h1);
            *(uint32_t*)&Cl[base]         = pk2(l0, l1);
            *(uint32_t*)&Ch[base + 8*DIM] = pk2(h2, h3);
            *(uint32_t*)&Cl[base + 8*DIM] = pk2(l2, l3);
        }
}

// ---------------------------------------------------------------------------
extern "C" void kernel_launch(void* const* d_in, const int* in_sizes, int n_in,
                              void* d_out, int out_size)
{
    const float* xin[3] = { (const float*)d_in[0], (const float*)d_in[1], (const float*)d_in[2] };
    const float* attnbias = (const float*)d_in[3];
    const float* paddings = (const float*)d_in[4];
    const float* ww[4] = { (const float*)d_in[5], (const float*)d_in[7],
                           (const float*)d_in[9], (const float*)d_in[11] };
    const float* wb[4] = { (const float*)d_in[6], (const float*)d_in[8],
                           (const float*)d_in[10], (const float*)d_in[12] };

    float* out  = (float*)d_out;
    float* attn = out + (size_t)MT * DIM;

    __nv_bfloat16 *xh, *xl, *twh, *twl, *ph, *pl, *vth, *vtl, *ch, *cl;
    float2 *partp, *msp;
    cudaGetSymbolAddress((void**)&xh, g_xh);   cudaGetSymbolAddress((void**)&xl, g_xl);
    cudaGetSymbolAddress((void**)&twh, g_twh); cudaGetSymbolAddress((void**)&twl, g_twl);
    cudaGetSymbolAddress((void**)&ph, g_ph);   cudaGetSymbolAddress((void**)&pl, g_pl);
    cudaGetSymbolAddress((void**)&vth, g_vth); cudaGetSymbolAddress((void**)&vtl, g_vtl);
    cudaGetSymbolAddress((void**)&ch, g_ch);   cudaGetSymbolAddress((void**)&cl, g_cl);
    cudaGetSymbolAddress((void**)&partp, g_part); cudaGetSymbolAddress((void**)&msp, g_ms);

    static int attr_done = 0;
    if (!attr_done) {
        cudaFuncSetAttribute(gemm_pipe_kernel<0>,  cudaFuncAttributeMaxDynamicSharedMemorySize, 81920);
        cudaFuncSetAttribute(gemm_pipe_kernel<1>,  cudaFuncAttributeMaxDynamicSharedMemorySize, 81920);
        cudaFuncSetAttribute(logits_fused_kernel,  cudaFuncAttributeMaxDynamicSharedMemorySize, 81920);
        cudaFuncSetAttribute(av_pipe_kernel,       cudaFuncAttributeMaxDynamicSharedMemorySize, 78848);
        attr_done = 1;
    }

    const size_t NX = (size_t)MT * DIM;
    const size_t NW = (size_t)DIM * DIM;

    for (int i = 0; i < 3; i++)
        split_kernel<<<NX/1024, 256>>>(xin[i], xh + i*NX, xl + i*NX);
    for (int i = 0; i < 4; i++)
        wtrans_kernel<<<dim3(32,32), dim3(32,8)>>>(ww[i], twh + i*NW, twl + i*NW);

    // QKV projections, batched
    gemm_pipe_kernel<0><<<dim3(8,32,3), 256, 81920>>>(
        xh, xl, twh, twl, wb[0], wb[1], wb[2], nullptr, ph, pl);

    __nv_bfloat16 *qh = ph, *ql = pl;
    __nv_bfloat16 *kh = ph + NX, *kl = pl + NX;
    __nv_bfloat16 *vh = ph + 2*NX, *vl = pl + 2*NX;

    vtrans_kernel<<<dim3(32, NBH), 256>>>(vh, vth);
    vtrans_kernel<<<dim3(32, NBH), 256>>>(vl, vtl);

    // logits + bias + mask + softmax partials
    logits_fused_kernel<<<dim3(16,16,NBH), 256, 81920>>>(
        qh, ql, kh, kl, attnbias, paddings, attn, partp);

    // merge partials -> (max, 1/sum) per row
    ms_reduce_kernel<<<(NBH*SS)/256, 256>>>(partp, msp);

    // AV: normalize + write weights + MMA
    av_pipe_kernel<<<dim3(16, NBH), 256, 78848>>>(attn, msp, vth, vtl, ch, cl);

    // output projection -> fp32 out
    gemm_pipe_kernel<1><<<dim3(8,32), 256, 81920>>>(
        ch, cl, twh + 3*NW, twl + 3*NW, wb[3], nullptr, nullptr, out, nullptr, nullptr);
}

// round 16
// speedup vs baseline: 1.3450x; 1.0037x over previous
#include <cuda_runtime.h>
#include <cuda_bf16.h>
#include <stdint.h>

#define BB  2
#define SS  2048
#define DIM 1024
#define HH  16
#define DD  64
#define MT  (BB*SS)
#define NBH (BB*HH)

// ---- device scratch ----
__device__ __nv_bfloat16 g_xh[3][MT*DIM], g_xl[3][MT*DIM];
__device__ __nv_bfloat16 g_twh[4][DIM*DIM], g_twl[4][DIM*DIM];
__device__ __nv_bfloat16 g_ph[3][NBH*SS*DD], g_pl[3][NBH*SS*DD];
__device__ __nv_bfloat16 g_vth[NBH*DD*SS], g_vtl[NBH*DD*SS];
__device__ __nv_bfloat16 g_ch[MT*DIM], g_cl[MT*DIM];
__device__ float2 g_part[(size_t)NBH*SS*16];
__device__ float2 g_ms[(size_t)NBH*SS];

#define STRD 40

// ---- helpers ----
__device__ __forceinline__ uint32_t s2u(const void* p){
    uint32_t a;
    asm("{ .reg .u64 t; cvta.to.shared.u64 t, %1; cvt.u32.u64 %0, t; }":"=r"(a):"l"(p));
    return a;
}
__device__ __forceinline__ void bsplit(float v, __nv_bfloat16& h, __nv_bfloat16& l){
    h = __float2bfloat16(v);
    l = __float2bfloat16(v - __bfloat162float(h));
}
__device__ __forceinline__ uint32_t pk2(__nv_bfloat16 a, __nv_bfloat16 b){
    __nv_bfloat162 t(a, b); return *(uint32_t*)&t;
}
__device__ __forceinline__ void ldmx4(uint32_t* r, uint32_t addr){
    asm volatile("ldmatrix.sync.aligned.m8n8.x4.shared.b16 {%0,%1,%2,%3}, [%4];"
        : "=r"(r[0]),"=r"(r[1]),"=r"(r[2]),"=r"(r[3]) : "r"(addr));
}
__device__ __forceinline__ void ldmx2(uint32_t* r, uint32_t addr){
    asm volatile("ldmatrix.sync.aligned.m8n8.x2.shared.b16 {%0,%1}, [%2];"
        : "=r"(r[0]),"=r"(r[1]) : "r"(addr));
}
// NOTE: no volatile — pure register op; lets NVVM/ptxas interleave MMAs with
// fragment loads and each other for better tensor-pipe occupancy.
__device__ __forceinline__ void mma16816(float* c, const uint32_t* a, const uint32_t* b){
    asm("mma.sync.aligned.m16n8k16.row.col.f32.bf16.bf16.f32 "
        "{%0,%1,%2,%3}, {%4,%5,%6,%7}, {%8,%9}, {%0,%1,%2,%3};"
        : "+f"(c[0]),"+f"(c[1]),"+f"(c[2]),"+f"(c[3])
        : "r"(a[0]),"r"(a[1]),"r"(a[2]),"r"(a[3]), "r"(b[0]),"r"(b[1]));
}
__device__ __forceinline__ void cpa16(uint32_t s, const void* g){
    asm volatile("cp.async.cg.shared.global [%0], [%1], 16;" :: "r"(s), "l"(g));
}
#define CPA_COMMIT() asm volatile("cp.async.commit_group;" ::: "memory")
#define CPA_WAIT1()  asm volatile("cp.async.wait_group 1;" ::: "memory")
#define CPA_WAIT0()  asm volatile("cp.async.wait_group 0;" ::: "memory")

// ---- warp-tile compute ----
// Product index p outermost: consecutive MMAs hit DIFFERENT accumulators
// (16-deep ILP). Per-accumulator order stays hh -> hl -> lh: bit-identical.
template<int WNT>
__device__ __forceinline__ void tile_compute(
    uint32_t aAh, uint32_t aAl, uint32_t aBh, uint32_t aBl,
    int wm, int wn, int lane, float c[4][WNT][4])
{
#pragma unroll
    for (int h = 0; h < 2; h++) {
        uint32_t fAh[4][4], fAl[4][4], fBh[WNT][2], fBl[WNT][2];
        const int ar = wm*64 + (lane & 15);
        const int ac = h*16 + ((lane >> 4) << 3);
#pragma unroll
        for (int mi = 0; mi < 4; mi++) {
            uint32_t off = (uint32_t)((ar + mi*16)*STRD + ac) * 2;
            ldmx4(fAh[mi], aAh + off);
            ldmx4(fAl[mi], aAl + off);
        }
        const int br = wn*(WNT*8) + (lane & 7);
        const int bc = h*16 + ((lane >> 3) & 1)*8;
#pragma unroll
        for (int ni = 0; ni < WNT; ni++) {
            uint32_t off = (uint32_t)((br + ni*8)*STRD + bc) * 2;
            ldmx2(fBh[ni], aBh + off);
            ldmx2(fBl[ni], aBl + off);
        }
#pragma unroll
        for (int p = 0; p < 3; p++)
#pragma unroll
            for (int mi = 0; mi < 4; mi++)
#pragma unroll
                for (int ni = 0; ni < WNT; ni++)
                    mma16816(c[mi][ni],
                             (p == 2) ? fAl[mi] : fAh[mi],
                             (p == 1) ? fBl[ni] : fBh[ni]);
    }
}

// ---- fp32 -> bf16 hi/lo split ----
__global__ void split_kernel(const float* __restrict__ x,
                             __nv_bfloat16* __restrict__ h,
                             __nv_bfloat16* __restrict__ l)
{
    int i = (blockIdx.x * blockDim.x + threadIdx.x) * 4;
    float4 v = *(const float4*)&x[i];
    __nv_bfloat16 h0,h1,h2,h3,l0,l1,l2,l3;
    bsplit(v.x,h0,l0); bsplit(v.y,h1,l1); bsplit(v.z,h2,l2); bsplit(v.w,h3,l3);
    uint2 hp = { pk2(h0,h1), pk2(h2,h3) };
    uint2 lp = { pk2(l0,l1), pk2(l2,l3) };
    *(uint2*)&h[i] = hp; *(uint2*)&l[i] = lp;
}

// ---- W[K,N] -> WT[N,K] hi/lo ----
__global__ void wtrans_kernel(const float* __restrict__ W,
                              __nv_bfloat16* __restrict__ Th,
                              __nv_bfloat16* __restrict__ Tl)
{
    __shared__ float t[32][33];
    int bx = blockIdx.x * 32, by = blockIdx.y * 32;
    int x = threadIdx.x, y = threadIdx.y;
    for (int yy = y; yy < 32; yy += 8)
        t[yy][x] = W[(size_t)(by + yy) * DIM + bx + x];
    __syncthreads();
    for (int yy = y; yy < 32; yy += 8) {
        __nv_bfloat16 h, l; bsplit(t[x][yy], h, l);
        Th[(size_t)(bx + yy) * DIM + by + x] = h;
        Tl[(size_t)(bx + yy) * DIM + by + x] = l;
    }
}

// ---- V [bh,s,d] -> VT [bh,d,s] (bf16), z picks hi/lo ----
__global__ void vtrans_kernel(const __nv_bfloat16* __restrict__ Vh,
                              const __nv_bfloat16* __restrict__ Vl,
                              __nv_bfloat16* __restrict__ VTh,
                              __nv_bfloat16* __restrict__ VTl)
{
    __shared__ __nv_bfloat16 t[64][65];
    const int z = blockIdx.z;
    const __nv_bfloat16* V  = z ? Vl  : Vh;
    __nv_bfloat16*       VT = z ? VTl : VTh;
    int bh = blockIdx.y, s0 = blockIdx.x * 64;
    int tid = threadIdx.x;
    for (int i = tid; i < 64*64; i += 256) {
        int r = i >> 6, c = i & 63;
        t[r][c] = V[((size_t)bh * SS + s0 + r) * DD + c];
    }
    __syncthreads();
    for (int i = tid; i < 64*64; i += 256) {
        int r = i >> 6, c = i & 63;
        VT[((size_t)bh * DD + r) * SS + s0 + c] = t[c][r];
    }
}

// ===========================================================================
// Projection GEMMs (cp.async 2-stage): MODE 0 QKV, MODE 1 out-proj.
// ===========================================================================
template<int MODE>
__global__ __launch_bounds__(256) void gemm_pipe_kernel(
    const __nv_bfloat16* __restrict__ Ah_, const __nv_bfloat16* __restrict__ Al_,
    const __nv_bfloat16* __restrict__ Bh_, const __nv_bfloat16* __restrict__ Bl_,
    const float* __restrict__ b0, const float* __restrict__ b1, const float* __restrict__ b2,
    float* __restrict__ outF,
    __nv_bfloat16* __restrict__ Oh_, __nv_bfloat16* __restrict__ Ol_)
{
    constexpr int NT = 32;
    extern __shared__ char sm[];
    const uint32_t sb = s2u(sm);
    const uint32_t aAH[2] = { sb,          sb + 10240 };
    const uint32_t aAL[2] = { sb + 20480,  sb + 30720 };
    const uint32_t aBH[2] = { sb + 40960,  sb + 51200 };
    const uint32_t aBL[2] = { sb + 61440,  sb + 71680 };

    const int tid = threadIdx.x, lane = tid & 31, wid = tid >> 5;
    const int wm = wid >> 2, wn = wid & 3;
    const size_t NX = (size_t)MT * DIM, NW = (size_t)DIM * DIM;

    const int z  = (MODE == 0) ? blockIdx.z : 0;
    const int n0 = blockIdx.x*128, m0 = blockIdx.y*128;

    const __nv_bfloat16* Abh = (MODE == 0 ? Ah_ + z*NX : Ah_) + (size_t)m0 * DIM;
    const __nv_bfloat16* Abl = (MODE == 0 ? Al_ + z*NX : Al_) + (size_t)m0 * DIM;
    const __nv_bfloat16* Bbh = (MODE == 0 ? Bh_ + z*NW : Bh_) + (size_t)n0 * DIM;
    const __nv_bfloat16* Bbl = (MODE == 0 ? Bl_ + z*NW : Bl_) + (size_t)n0 * DIM;
    const float* bias = (MODE == 0) ? (z == 0 ? b0 : (z == 1 ? b1 : b2)) : b0;

    float c[4][4][4] = {};

    auto load_stage = [&](int st, int k0){
        for (int idx = tid; idx < 512; idx += 256) {
            int r = idx >> 2, cc = idx & 3;
            uint32_t so = (uint32_t)r*80 + cc*16;
            size_t go = (size_t)r*DIM + k0 + cc*8;
            cpa16(aAH[st] + so, Abh + go);
            cpa16(aAL[st] + so, Abl + go);
            cpa16(aBH[st] + so, Bbh + go);
            cpa16(aBL[st] + so, Bbl + go);
        }
    };

    load_stage(0, 0);  CPA_COMMIT();
    load_stage(1, 32); CPA_COMMIT();

    for (int kt = 0; kt < NT; kt++) {
        if (kt + 1 < NT) { CPA_WAIT1(); } else { CPA_WAIT0(); }
        __syncthreads();
        const int st = kt & 1;
        tile_compute<4>(aAH[st], aAL[st], aBH[st], aBL[st], wm, wn, lane, c);
        __syncthreads();
        if (kt + 2 < NT) { load_stage(st, (kt + 2) * 32); CPA_COMMIT(); }
    }

    const int g = lane >> 2, tg = lane & 3;
#pragma unroll
    for (int mi = 0; mi < 4; mi++)
#pragma unroll
        for (int ni = 0; ni < 4; ni++) {
            const int m = m0 + wm*64 + mi*16 + g;
            const int n = n0 + wn*32 + ni*8 + tg*2;
            const float v00 = c[mi][ni][0], v01 = c[mi][ni][1];
            const float v10 = c[mi][ni][2], v11 = c[mi][ni][3];
            const float q0 = bias[n], q1 = bias[n+1];
            if (MODE == 1) {
                float2 r0 = { v00 + q0, v01 + q1 };
                float2 r1 = { v10 + q0, v11 + q1 };
                *(float2*)&outF[(size_t)m*DIM + n]     = r0;
                *(float2*)&outF[(size_t)(m+8)*DIM + n] = r1;
            } else {
                const int b = m >> 11, hd = n >> 6, d = n & 63;
                const size_t base = z*NX + (((size_t)(b*HH + hd))*SS + (m & 2047))*DD + d;
                __nv_bfloat16 h0,h1,h2,h3,l0,l1,l2,l3;
                bsplit(v00 + q0, h0, l0); bsplit(v01 + q1, h1, l1);
                bsplit(v10 + q0, h2, l2); bsplit(v11 + q1, h3, l3);
                *(uint32_t*)&Oh_[base]        = pk2(h0, h1);
                *(uint32_t*)&Ol_[base]        = pk2(l0, l1);
                *(uint32_t*)&Oh_[base + 8*DD] = pk2(h2, h3);
                *(uint32_t*)&Ol_[base + 8*DD] = pk2(l2, l3);
            }
        }
}

// ===========================================================================
// Logits fused: QK^T via cp.async 2-stage, epilogue applies scale+bias+mask
// from gmem, writes biased logits + per-stile partials. grid (16,16,32).
// ===========================================================================
__global__ __launch_bounds__(256) void logits_fused_kernel(
    const __nv_bfloat16* __restrict__ Qh, const __nv_bfloat16* __restrict__ Ql,
    const __nv_bfloat16* __restrict__ Kh, const __nv_bfloat16* __restrict__ Kl,
    const float* __restrict__ bias4d, const float* __restrict__ pad,
    float* __restrict__ attn, float2* __restrict__ part)
{
    extern __shared__ char sm[];
    const uint32_t sb = s2u(sm);
    const uint32_t aAH[2] = { sb,          sb + 10240 };
    const uint32_t aAL[2] = { sb + 20480,  sb + 30720 };
    const uint32_t aBH[2] = { sb + 40960,  sb + 51200 };
    const uint32_t aBL[2] = { sb + 61440,  sb + 71680 };

    const int tid = threadIdx.x, lane = tid & 31, wid = tid >> 5;
    const int wm = wid >> 2, wn = wid & 3;
    const int bh = blockIdx.z, b = bh >> 4;
    const int stile = blockIdx.x;
    const int n0 = stile*128, m0 = blockIdx.y*128;

    const __nv_bfloat16* Abh = Qh + ((size_t)bh*SS + m0) * DD;
    const __nv_bfloat16* Abl = Ql + ((size_t)bh*SS + m0) * DD;
    const __nv_bfloat16* Bbh = Kh + ((size_t)bh*SS + n0) * DD;
    const __nv_bfloat16* Bbl = Kl + ((size_t)bh*SS + n0) * DD;

    auto load_stage = [&](int st, int k0){
        for (int idx = tid; idx < 512; idx += 256) {
            int r = idx >> 2, cc = idx & 3;
            uint32_t so = (uint32_t)r*80 + cc*16;
            size_t go = (size_t)r*DD + k0 + cc*8;
            cpa16(aAH[st] + so, Abh + go);
            cpa16(aAL[st] + so, Abl + go);
            cpa16(aBH[st] + so, Bbh + go);
            cpa16(aBL[st] + so, Bbl + go);
        }
    };

    load_stage(0, 0);  CPA_COMMIT();
    load_stage(1, 32); CPA_COMMIT();

    float c[4][4][4] = {};
    CPA_WAIT1();
    __syncthreads();
    tile_compute<4>(aAH[0], aAL[0], aBH[0], aBL[0], wm, wn, lane, c);
    CPA_WAIT0();
    __syncthreads();
    tile_compute<4>(aAH[1], aAL[1], aBH[1], aBL[1], wm, wn, lane, c);
    __syncthreads();

    // epilogue: bias+mask from gmem, write logits, partial (max,sumexp)
    float2* spair = (float2*)sm;   // reuse data smem: [4][128]
    const int g = lane >> 2, tg = lane & 3;

#pragma unroll
    for (int mi = 0; mi < 4; mi++)
#pragma unroll
        for (int half = 0; half < 2; half++) {
            const int rloc = wm*64 + mi*16 + half*8 + g;
            const int t = m0 + rloc;
            const float mt = 1.0f - pad[b*SS + t];
            const float* bp = &bias4d[((size_t)bh*SS + t)*SS + n0];
            float* ap = &attn[((size_t)bh*SS + t)*SS + n0];
            float vv[8];
#pragma unroll
            for (int ni = 0; ni < 4; ni++) {
                const int nl = wn*32 + ni*8 + tg*2;
                const float ms0 = 1.0f - pad[b*SS + n0 + nl];
                const float ms1 = 1.0f - pad[b*SS + n0 + nl + 1];
                float x0 = c[mi][ni][half*2+0]*0.125f + bp[nl]   - 1e9f*(1.0f - mt*ms0);
                float x1 = c[mi][ni][half*2+1]*0.125f + bp[nl+1] - 1e9f*(1.0f - mt*ms1);
                vv[ni*2]   = x0;
                vv[ni*2+1] = x1;
                float2 w = { x0, x1 };
                *(float2*)&ap[nl] = w;
            }
            float mx = vv[0];
#pragma unroll
            for (int j = 1; j < 8; j++) mx = fmaxf(mx, vv[j]);
            mx = fmaxf(mx, __shfl_xor_sync(~0u, mx, 1));
            mx = fmaxf(mx, __shfl_xor_sync(~0u, mx, 2));
            float se = 0.f;
#pragma unroll
            for (int j = 0; j < 8; j++) se += __expf(vv[j] - mx);
            se += __shfl_xor_sync(~0u, se, 1);
            se += __shfl_xor_sync(~0u, se, 2);
            if (tg == 0) spair[wn*128 + rloc] = make_float2(mx, se);
        }
    __syncthreads();

    if (tid < 128) {
        float2 p0 = spair[tid], p1 = spair[128 + tid];
        float2 p2 = spair[256 + tid], p3 = spair[384 + tid];
        float m01 = fmaxf(p0.x, p1.x), m23 = fmaxf(p2.x, p3.x);
        float m = fmaxf(m01, m23);
        float s = p0.y*__expf(p0.x - m) + p1.y*__expf(p1.x - m)
                + p2.y*__expf(p2.x - m) + p3.y*__expf(p3.x - m);
        part[(((size_t)bh*SS) + m0 + tid)*16 + stile] = make_float2(m, s);
    }
}

// ---- merge 16 partials per row -> (max, 1/sum) ----
__global__ void ms_reduce_kernel(const float2* __restrict__ part,
                                 float2* __restrict__ ms)
{
    const int row = blockIdx.x * 256 + threadIdx.x;
    const float2* p = part + (size_t)row * 16;
    float2 v[16];
#pragma unroll
    for (int i = 0; i < 8; i++) {
        float4 a = *(const float4*)&p[i*2];
        v[i*2]   = make_float2(a.x, a.y);
        v[i*2+1] = make_float2(a.z, a.w);
    }
    float m = v[0].x;
#pragma unroll
    for (int i = 1; i < 16; i++) m = fmaxf(m, v[i].x);
    float s = 0.f;
#pragma unroll
    for (int i = 0; i < 16; i++) s += v[i].y * __expf(v[i].x - m);
    ms[row] = make_float2(m, 1.0f / s);
}

// ===========================================================================
// AV fused: normalize + write weights + split + MMA. grid (16,32). dyn 78848.
// ===========================================================================
__global__ __launch_bounds__(256) void av_pipe_kernel(
    float* __restrict__ attn,
    const float2* __restrict__ ms,
    const __nv_bfloat16* __restrict__ VTh, const __nv_bfloat16* __restrict__ VTl,
    __nv_bfloat16* __restrict__ Ch, __nv_bfloat16* __restrict__ Cl)
{
    extern __shared__ char sm[];
    const uint32_t sb = s2u(sm);
    const uint32_t aAF[2] = { sb, sb + 18432 };
    const uint32_t aAH = sb + 36864, aAL = sb + 47104;
    const uint32_t aBH[2] = { sb + 57344, sb + 62464 };
    const uint32_t aBL[2] = { sb + 67584, sb + 72704 };
    float2* sms = (float2*)(sm + 77824);

    const int tid = threadIdx.x, lane = tid & 31, wid = tid >> 5;
    const int wm = wid >> 2, wn = wid & 3;
    const int bh = blockIdx.y, b = bh >> 4, hd = bh & 15;
    const int m0 = blockIdx.x * 128;

    float* Abf = attn + ((size_t)bh*SS + m0) * SS;
    const __nv_bfloat16* Bbh = VTh + (size_t)bh*DD*SS;
    const __nv_bfloat16* Bbl = VTl + (size_t)bh*DD*SS;

    if (tid < 128) sms[tid] = ms[(size_t)bh*SS + m0 + tid];

    float c[4][2][4] = {};

    auto load_stage = [&](int st, int k0){
        for (int idx = tid; idx < 1024; idx += 256) {
            int r = idx >> 3, cc = idx & 7;
            cpa16(aAF[st] + (uint32_t)r*144 + cc*16, Abf + (size_t)r*SS + k0 + cc*4);
        }
        for (int idx = tid; idx < 256; idx += 256) {
            int r = idx >> 2, cc = idx & 3;
            uint32_t so = (uint32_t)r*80 + cc*16;
            size_t go = (size_t)r*SS + k0 + cc*8;
            cpa16(aBH[st] + so, Bbh + go);
            cpa16(aBL[st] + so, Bbl + go);
        }
    };

    load_stage(0, 0);  CPA_COMMIT();
    load_stage(1, 32); CPA_COMMIT();

    for (int kt = 0; kt < 64; kt++) {
        if (kt + 1 < 64) { CPA_WAIT1(); } else { CPA_WAIT0(); }
        __syncthreads();
        const int st = kt & 1;
        const int k0 = kt * 32;
        for (int idx = tid; idx < 1024; idx += 256) {
            int r = idx >> 3, cc = idx & 7;
            float4 w = *(const float4*)(sm + st*18432 + r*144 + cc*16);
            float2 q = sms[r];
            w.x = __expf(w.x - q.x) * q.y;
            w.y = __expf(w.y - q.x) * q.y;
            w.z = __expf(w.z - q.x) * q.y;
            w.w = __expf(w.w - q.x) * q.y;
            *(float4*)&Abf[(size_t)r*SS + k0 + cc*4] = w;
            __nv_bfloat16 h0,h1,h2,h3,l0,l1,l2,l3;
            bsplit(w.x,h0,l0); bsplit(w.y,h1,l1); bsplit(w.z,h2,l2); bsplit(w.w,h3,l3);
            uint2 hp = { pk2(h0,h1), pk2(h2,h3) };
            uint2 lp = { pk2(l0,l1), pk2(l2,l3) };
            *(uint2*)(sm + 36864 + r*80 + cc*8) = hp;
            *(uint2*)(sm + 47104 + r*80 + cc*8) = lp;
        }
        __syncthreads();
        tile_compute<2>(aAH, aAL, aBH[st], aBL[st], wm, wn, lane, c);
        __syncthreads();
        if (kt + 2 < 64) { load_stage(st, (kt + 2) * 32); CPA_COMMIT(); }
    }

    const int g = lane >> 2, tg = lane & 3;
#pragma unroll
    for (int mi = 0; mi < 4; mi++)
#pragma unroll
        for (int ni = 0; ni < 2; ni++) {
            const int m = m0 + wm*64 + mi*16 + g;
            const int n = wn*16 + ni*8 + tg*2;
            const size_t base = ((size_t)(b*SS + m))*DIM + hd*DD + n;
            __nv_bfloat16 h0,h1,h2,h3,l0,l1,l2,l3;
            bsplit(c[mi][ni][0], h0, l0); bsplit(c[mi][ni][1], h1, l1);
            bsplit(c[mi][ni][2], h2, l2); bsplit(c[mi][ni][3], h3, l3);
            *(uint32_t*)&Ch[base]         = pk2(h0, h1);
            *(uint32_t*)&Cl[base]         = pk2(l0, l1);
            *(uint32_t*)&Ch[base + 8*DIM] = pk2(h2, h3);
            *(uint32_t*)&Cl[base + 8*DIM] = pk2(l2, l3);
        }
}

// ---------------------------------------------------------------------------
extern "C" void kernel_launch(void* const* d_in, const int* in_sizes, int n_in,
                              void* d_out, int out_size)
{
    const float* xin[3] = { (const float*)d_in[0], (const float*)d_in[1], (const float*)d_in[2] };
    const float* attnbias = (const float*)d_in[3];
    const float* paddings = (const float*)d_in[4];
    const float* ww[4] = { (const float*)d_in[5], (const float*)d_in[7],
                           (const float*)d_in[9], (const float*)d_in[11] };
    const float* wb[4] = { (const float*)d_in[6], (const float*)d_in[8],
                           (const float*)d_in[10], (const float*)d_in[12] };

    float* out  = (float*)d_out;
    float* attn = out + (size_t)MT * DIM;

    __nv_bfloat16 *xh, *xl, *twh, *twl, *ph, *pl, *vth, *vtl, *ch, *cl;
    float2 *partp, *msp;
    cudaGetSymbolAddress((void**)&xh, g_xh);   cudaGetSymbolAddress((void**)&xl, g_xl);
    cudaGetSymbolAddress((void**)&twh, g_twh); cudaGetSymbolAddress((void**)&twl, g_twl);
    cudaGetSymbolAddress((void**)&ph, g_ph);   cudaGetSymbolAddress((void**)&pl, g_pl);
    cudaGetSymbolAddress((void**)&vth, g_vth); cudaGetSymbolAddress((void**)&vtl, g_vtl);
    cudaGetSymbolAddress((void**)&ch, g_ch);   cudaGetSymbolAddress((void**)&cl, g_cl);
    cudaGetSymbolAddress((void**)&partp, g_part); cudaGetSymbolAddress((void**)&msp, g_ms);

    static int attr_done = 0;
    if (!attr_done) {
        cudaFuncSetAttribute(gemm_pipe_kernel<0>,  cudaFuncAttributeMaxDynamicSharedMemorySize, 81920);
        cudaFuncSetAttribute(gemm_pipe_kernel<1>,  cudaFuncAttributeMaxDynamicSharedMemorySize, 81920);
        cudaFuncSetAttribute(logits_fused_kernel,  cudaFuncAttributeMaxDynamicSharedMemorySize, 81920);
        cudaFuncSetAttribute(av_pipe_kernel,       cudaFuncAttributeMaxDynamicSharedMemorySize, 78848);
        attr_done = 1;
    }

    const size_t NX = (size_t)MT * DIM;
    const size_t NW = (size_t)DIM * DIM;

    for (int i = 0; i < 3; i++)
        split_kernel<<<NX/1024, 256>>>(xin[i], xh + i*NX, xl + i*NX);
    for (int i = 0; i < 4; i++)
        wtrans_kernel<<<dim3(32,32), dim3(32,8)>>>(ww[i], twh + i*NW, twl + i*NW);

    // QKV projections, batched
    gemm_pipe_kernel<0><<<dim3(8,32,3), 256, 81920>>>(
        xh, xl, twh, twl, wb[0], wb[1], wb[2], nullptr, ph, pl);

    __nv_bfloat16 *qh = ph, *ql = pl;
    __nv_bfloat16 *kh = ph + NX, *kl = pl + NX;
    __nv_bfloat16 *vh = ph + 2*NX, *vl = pl + 2*NX;

    // V transpose, hi+lo in one launch
    vtrans_kernel<<<dim3(32, NBH, 2), 256>>>(vh, vl, vth, vtl);

    // logits + bias + mask + softmax partials
    logits_fused_kernel<<<dim3(16,16,NBH), 256, 81920>>>(
        qh, ql, kh, kl, attnbias, paddings, attn, partp);

    // merge partials -> (max, 1/sum) per row
    ms_reduce_kernel<<<(NBH*SS)/256, 256>>>(partp, msp);

    // AV: normalize + write weights + MMA
    av_pipe_kernel<<<dim3(16, NBH), 256, 78848>>>(attn, msp, vth, vtl, ch, cl);

    // output projection -> fp32 out
    gemm_pipe_kernel<1><<<dim3(8,32), 256, 81920>>>(
        ch, cl, twh + 3*NW, twl + 3*NW, wb[3], nullptr, nullptr, out, nullptr, nullptr);
}

// round 17
// speedup vs baseline: 1.3791x; 1.0253x over previous
#include <cuda_runtime.h>
#include <cuda_bf16.h>
#include <stdint.h>

#define BB  2
#define SS  2048
#define DIM 1024
#define HH  16
#define DD  64
#define MT  (BB*SS)
#define NBH (BB*HH)

// ---- device scratch ----
__device__ __nv_bfloat16 g_twh[4][DIM*DIM], g_twl[4][DIM*DIM];
__device__ __nv_bfloat16 g_ph[3][NBH*SS*DD], g_pl[3][NBH*SS*DD];
__device__ __nv_bfloat16 g_vth[NBH*DD*SS], g_vtl[NBH*DD*SS];
__device__ __nv_bfloat16 g_ch[MT*DIM], g_cl[MT*DIM];
__device__ float2 g_part[(size_t)NBH*SS*16];
__device__ float2 g_ms[(size_t)NBH*SS];

#define STRD 40

// ---- helpers ----
__device__ __forceinline__ uint32_t s2u(const void* p){
    uint32_t a;
    asm("{ .reg .u64 t; cvta.to.shared.u64 t, %1; cvt.u32.u64 %0, t; }":"=r"(a):"l"(p));
    return a;
}
__device__ __forceinline__ void bsplit(float v, __nv_bfloat16& h, __nv_bfloat16& l){
    h = __float2bfloat16(v);
    l = __float2bfloat16(v - __bfloat162float(h));
}
__device__ __forceinline__ uint32_t pk2(__nv_bfloat16 a, __nv_bfloat16 b){
    __nv_bfloat162 t(a, b); return *(uint32_t*)&t;
}
__device__ __forceinline__ void ldmx4(uint32_t* r, uint32_t addr){
    asm volatile("ldmatrix.sync.aligned.m8n8.x4.shared.b16 {%0,%1,%2,%3}, [%4];"
        : "=r"(r[0]),"=r"(r[1]),"=r"(r[2]),"=r"(r[3]) : "r"(addr));
}
__device__ __forceinline__ void ldmx2(uint32_t* r, uint32_t addr){
    asm volatile("ldmatrix.sync.aligned.m8n8.x2.shared.b16 {%0,%1}, [%2];"
        : "=r"(r[0]),"=r"(r[1]) : "r"(addr));
}
// no volatile: pure register op; lets the compiler interleave MMAs freely
__device__ __forceinline__ void mma16816(float* c, const uint32_t* a, const uint32_t* b){
    asm("mma.sync.aligned.m16n8k16.row.col.f32.bf16.bf16.f32 "
        "{%0,%1,%2,%3}, {%4,%5,%6,%7}, {%8,%9}, {%0,%1,%2,%3};"
        : "+f"(c[0]),"+f"(c[1]),"+f"(c[2]),"+f"(c[3])
        : "r"(a[0]),"r"(a[1]),"r"(a[2]),"r"(a[3]), "r"(b[0]),"r"(b[1]));
}
__device__ __forceinline__ void cpa16(uint32_t s, const void* g){
    asm volatile("cp.async.cg.shared.global [%0], [%1], 16;" :: "r"(s), "l"(g));
}
#define CPA_COMMIT() asm volatile("cp.async.commit_group;" ::: "memory")
#define CPA_WAIT1()  asm volatile("cp.async.wait_group 1;" ::: "memory")
#define CPA_WAIT0()  asm volatile("cp.async.wait_group 0;" ::: "memory")

// ---- warp-tile compute (p outermost: 16-deep accumulator ILP) ----
template<int WNT>
__device__ __forceinline__ void tile_compute(
    uint32_t aAh, uint32_t aAl, uint32_t aBh, uint32_t aBl,
    int wm, int wn, int lane, float c[4][WNT][4])
{
#pragma unroll
    for (int h = 0; h < 2; h++) {
        uint32_t fAh[4][4], fAl[4][4], fBh[WNT][2], fBl[WNT][2];
        const int ar = wm*64 + (lane & 15);
        const int ac = h*16 + ((lane >> 4) << 3);
#pragma unroll
        for (int mi = 0; mi < 4; mi++) {
            uint32_t off = (uint32_t)((ar + mi*16)*STRD + ac) * 2;
            ldmx4(fAh[mi], aAh + off);
            ldmx4(fAl[mi], aAl + off);
        }
        const int br = wn*(WNT*8) + (lane & 7);
        const int bc = h*16 + ((lane >> 3) & 1)*8;
#pragma unroll
        for (int ni = 0; ni < WNT; ni++) {
            uint32_t off = (uint32_t)((br + ni*8)*STRD + bc) * 2;
            ldmx2(fBh[ni], aBh + off);
            ldmx2(fBl[ni], aBl + off);
        }
#pragma unroll
        for (int p = 0; p < 3; p++)
#pragma unroll
            for (int mi = 0; mi < 4; mi++)
#pragma unroll
                for (int ni = 0; ni < WNT; ni++)
                    mma16816(c[mi][ni],
                             (p == 2) ? fAl[mi] : fAh[mi],
                             (p == 1) ? fBl[ni] : fBh[ni]);
    }
}

// ---- W[K,N] -> WT[N,K] hi/lo ----
__global__ void wtrans_kernel(const float* __restrict__ W,
                              __nv_bfloat16* __restrict__ Th,
                              __nv_bfloat16* __restrict__ Tl)
{
    __shared__ float t[32][33];
    int bx = blockIdx.x * 32, by = blockIdx.y * 32;
    int x = threadIdx.x, y = threadIdx.y;
    for (int yy = y; yy < 32; yy += 8)
        t[yy][x] = W[(size_t)(by + yy) * DIM + bx + x];
    __syncthreads();
    for (int yy = y; yy < 32; yy += 8) {
        __nv_bfloat16 h, l; bsplit(t[x][yy], h, l);
        Th[(size_t)(bx + yy) * DIM + by + x] = h;
        Tl[(size_t)(bx + yy) * DIM + by + x] = l;
    }
}

// ---- V [bh,s,d] -> VT [bh,d,s] (bf16), z picks hi/lo ----
__global__ void vtrans_kernel(const __nv_bfloat16* __restrict__ Vh,
                              const __nv_bfloat16* __restrict__ Vl,
                              __nv_bfloat16* __restrict__ VTh,
                              __nv_bfloat16* __restrict__ VTl)
{
    __shared__ __nv_bfloat16 t[64][65];
    const int z = blockIdx.z;
    const __nv_bfloat16* V  = z ? Vl  : Vh;
    __nv_bfloat16*       VT = z ? VTl : VTh;
    int bh = blockIdx.y, s0 = blockIdx.x * 64;
    int tid = threadIdx.x;
    for (int i = tid; i < 64*64; i += 256) {
        int r = i >> 6, c = i & 63;
        t[r][c] = V[((size_t)bh * SS + s0 + r) * DD + c];
    }
    __syncthreads();
    for (int i = tid; i < 64*64; i += 256) {
        int r = i >> 6, c = i & 63;
        VT[((size_t)bh * DD + r) * SS + s0 + c] = t[c][r];
    }
}

// ===========================================================================
// QKV GEMM with fused fp32->bf16 split of A (cp.async 2-stage on fp32 A + B).
// grid (8,32,3). dyn smem = 98304. 2 CTA/SM.
// ===========================================================================
#define Q_SMEM 98304
__global__ __launch_bounds__(256) void qkv_pipe_kernel(
    const float* __restrict__ x0, const float* __restrict__ x1,
    const float* __restrict__ x2,
    const __nv_bfloat16* __restrict__ Bh_, const __nv_bfloat16* __restrict__ Bl_,
    const float* __restrict__ b0, const float* __restrict__ b1,
    const float* __restrict__ b2,
    __nv_bfloat16* __restrict__ Oh_, __nv_bfloat16* __restrict__ Ol_)
{
    extern __shared__ char sm[];
    const uint32_t sb = s2u(sm);
    const uint32_t aAF[2] = { sb, sb + 18432 };          // fp32 128x32, stride 144B
    const uint32_t aAH = sb + 36864, aAL = sb + 47104;   // bf16, stride 80B
    const uint32_t aBH[2] = { sb + 57344, sb + 67584 };
    const uint32_t aBL[2] = { sb + 77824, sb + 88064 };

    const int tid = threadIdx.x, lane = tid & 31, wid = tid >> 5;
    const int wm = wid >> 2, wn = wid & 3;
    const size_t NX = (size_t)MT * DIM, NW = (size_t)DIM * DIM;
    const int z = blockIdx.z;
    const int n0 = blockIdx.x*128, m0 = blockIdx.y*128;

    const float* Abf = ((z == 0) ? x0 : (z == 1) ? x1 : x2) + (size_t)m0 * DIM;
    const __nv_bfloat16* Bbh = Bh_ + z*NW + (size_t)n0 * DIM;
    const __nv_bfloat16* Bbl = Bl_ + z*NW + (size_t)n0 * DIM;
    const float* bias = (z == 0) ? b0 : (z == 1) ? b1 : b2;

    float c[4][4][4] = {};

    auto load_stage = [&](int st, int k0){
        for (int idx = tid; idx < 1024; idx += 256) {
            int r = idx >> 3, cc = idx & 7;
            cpa16(aAF[st] + (uint32_t)r*144 + cc*16, Abf + (size_t)r*DIM + k0 + cc*4);
        }
        for (int idx = tid; idx < 512; idx += 256) {
            int r = idx >> 2, cc = idx & 3;
            uint32_t so = (uint32_t)r*80 + cc*16;
            size_t go = (size_t)r*DIM + k0 + cc*8;
            cpa16(aBH[st] + so, Bbh + go);
            cpa16(aBL[st] + so, Bbl + go);
        }
    };

    load_stage(0, 0);  CPA_COMMIT();
    load_stage(1, 32); CPA_COMMIT();

    for (int kt = 0; kt < 32; kt++) {
        if (kt + 1 < 32) { CPA_WAIT1(); } else { CPA_WAIT0(); }
        __syncthreads();
        const int st = kt & 1;
        // convert fp32 stage -> bf16 hi/lo (bit-identical to split_kernel)
        for (int idx = tid; idx < 1024; idx += 256) {
            int r = idx >> 3, cc = idx & 7;
            float4 w = *(const float4*)(sm + st*18432 + r*144 + cc*16);
            __nv_bfloat16 h0,h1,h2,h3,l0,l1,l2,l3;
            bsplit(w.x,h0,l0); bsplit(w.y,h1,l1); bsplit(w.z,h2,l2); bsplit(w.w,h3,l3);
            uint2 hp = { pk2(h0,h1), pk2(h2,h3) };
            uint2 lp = { pk2(l0,l1), pk2(l2,l3) };
            *(uint2*)(sm + 36864 + r*80 + cc*8) = hp;
            *(uint2*)(sm + 47104 + r*80 + cc*8) = lp;
        }
        __syncthreads();
        tile_compute<4>(aAH, aAL, aBH[st], aBL[st], wm, wn, lane, c);
        __syncthreads();
        if (kt + 2 < 32) { load_stage(st, (kt + 2) * 32); CPA_COMMIT(); }
    }

    const int g = lane >> 2, tg = lane & 3;
#pragma unroll
    for (int mi = 0; mi < 4; mi++)
#pragma unroll
        for (int ni = 0; ni < 4; ni++) {
            const int m = m0 + wm*64 + mi*16 + g;
            const int n = n0 + wn*32 + ni*8 + tg*2;
            const float q0 = bias[n], q1 = bias[n+1];
            const float v00 = c[mi][ni][0] + q0, v01 = c[mi][ni][1] + q1;
            const float v10 = c[mi][ni][2] + q0, v11 = c[mi][ni][3] + q1;
            const int b = m >> 11, hd = n >> 6, d = n & 63;
            const size_t base = z*NX + (((size_t)(b*HH + hd))*SS + (m & 2047))*DD + d;
            __nv_bfloat16 h0,h1,h2,h3,l0,l1,l2,l3;
            bsplit(v00, h0, l0); bsplit(v01, h1, l1);
            bsplit(v10, h2, l2); bsplit(v11, h3, l3);
            *(uint32_t*)&Oh_[base]        = pk2(h0, h1);
            *(uint32_t*)&Ol_[base]        = pk2(l0, l1);
            *(uint32_t*)&Oh_[base + 8*DD] = pk2(h2, h3);
            *(uint32_t*)&Ol_[base + 8*DD] = pk2(l2, l3);
        }
}

// ===========================================================================
// Out-proj GEMM (bf16 A, cp.async 2-stage): fp32 out (+bias). grid (8,32).
// ===========================================================================
__global__ __launch_bounds__(256) void gemm_pipe_kernel(
    const __nv_bfloat16* __restrict__ Ah_, const __nv_bfloat16* __restrict__ Al_,
    const __nv_bfloat16* __restrict__ Bh_, const __nv_bfloat16* __restrict__ Bl_,
    const float* __restrict__ bias,
    float* __restrict__ outF)
{
    constexpr int NT = 32;
    extern __shared__ char sm[];
    const uint32_t sb = s2u(sm);
    const uint32_t aAH[2] = { sb,          sb + 10240 };
    const uint32_t aAL[2] = { sb + 20480,  sb + 30720 };
    const uint32_t aBH[2] = { sb + 40960,  sb + 51200 };
    const uint32_t aBL[2] = { sb + 61440,  sb + 71680 };

    const int tid = threadIdx.x, lane = tid & 31, wid = tid >> 5;
    const int wm = wid >> 2, wn = wid & 3;
    const int n0 = blockIdx.x*128, m0 = blockIdx.y*128;

    const __nv_bfloat16* Abh = Ah_ + (size_t)m0 * DIM;
    const __nv_bfloat16* Abl = Al_ + (size_t)m0 * DIM;
    const __nv_bfloat16* Bbh = Bh_ + (size_t)n0 * DIM;
    const __nv_bfloat16* Bbl = Bl_ + (size_t)n0 * DIM;

    float c[4][4][4] = {};

    auto load_stage = [&](int st, int k0){
        for (int idx = tid; idx < 512; idx += 256) {
            int r = idx >> 2, cc = idx & 3;
            uint32_t so = (uint32_t)r*80 + cc*16;
            size_t go = (size_t)r*DIM + k0 + cc*8;
            cpa16(aAH[st] + so, Abh + go);
            cpa16(aAL[st] + so, Abl + go);
            cpa16(aBH[st] + so, Bbh + go);
            cpa16(aBL[st] + so, Bbl + go);
        }
    };

    load_stage(0, 0);  CPA_COMMIT();
    load_stage(1, 32); CPA_COMMIT();

    for (int kt = 0; kt < NT; kt++) {
        if (kt + 1 < NT) { CPA_WAIT1(); } else { CPA_WAIT0(); }
        __syncthreads();
        const int st = kt & 1;
        tile_compute<4>(aAH[st], aAL[st], aBH[st], aBL[st], wm, wn, lane, c);
        __syncthreads();
        if (kt + 2 < NT) { load_stage(st, (kt + 2) * 32); CPA_COMMIT(); }
    }

    const int g = lane >> 2, tg = lane & 3;
#pragma unroll
    for (int mi = 0; mi < 4; mi++)
#pragma unroll
        for (int ni = 0; ni < 4; ni++) {
            const int m = m0 + wm*64 + mi*16 + g;
            const int n = n0 + wn*32 + ni*8 + tg*2;
            const float q0 = bias[n], q1 = bias[n+1];
            float2 r0 = { c[mi][ni][0] + q0, c[mi][ni][1] + q1 };
            float2 r1 = { c[mi][ni][2] + q0, c[mi][ni][3] + q1 };
            *(float2*)&outF[(size_t)m*DIM + n]     = r0;
            *(float2*)&outF[(size_t)(m+8)*DIM + n] = r1;
        }
}

// ===========================================================================
// Logits fused: QK^T, epilogue scale+bias+mask from gmem, biased logits +
// per-stile partials. grid (16,16,32). dyn 81920.
// ===========================================================================
__global__ __launch_bounds__(256) void logits_fused_kernel(
    const __nv_bfloat16* __restrict__ Qh, const __nv_bfloat16* __restrict__ Ql,
    const __nv_bfloat16* __restrict__ Kh, const __nv_bfloat16* __restrict__ Kl,
    const float* __restrict__ bias4d, const float* __restrict__ pad,
    float* __restrict__ attn, float2* __restrict__ part)
{
    extern __shared__ char sm[];
    const uint32_t sb = s2u(sm);
    const uint32_t aAH[2] = { sb,          sb + 10240 };
    const uint32_t aAL[2] = { sb + 20480,  sb + 30720 };
    const uint32_t aBH[2] = { sb + 40960,  sb + 51200 };
    const uint32_t aBL[2] = { sb + 61440,  sb + 71680 };

    const int tid = threadIdx.x, lane = tid & 31, wid = tid >> 5;
    const int wm = wid >> 2, wn = wid & 3;
    const int bh = blockIdx.z, b = bh >> 4;
    const int stile = blockIdx.x;
    const int n0 = stile*128, m0 = blockIdx.y*128;

    const __nv_bfloat16* Abh = Qh + ((size_t)bh*SS + m0) * DD;
    const __nv_bfloat16* Abl = Ql + ((size_t)bh*SS + m0) * DD;
    const __nv_bfloat16* Bbh = Kh + ((size_t)bh*SS + n0) * DD;
    const __nv_bfloat16* Bbl = Kl + ((size_t)bh*SS + n0) * DD;

    auto load_stage = [&](int st, int k0){
        for (int idx = tid; idx < 512; idx += 256) {
            int r = idx >> 2, cc = idx & 3;
            uint32_t so = (uint32_t)r*80 + cc*16;
            size_t go = (size_t)r*DD + k0 + cc*8;
            cpa16(aAH[st] + so, Abh + go);
            cpa16(aAL[st] + so, Abl + go);
            cpa16(aBH[st] + so, Bbh + go);
            cpa16(aBL[st] + so, Bbl + go);
        }
    };

    load_stage(0, 0);  CPA_COMMIT();
    load_stage(1, 32); CPA_COMMIT();

    float c[4][4][4] = {};
    CPA_WAIT1();
    __syncthreads();
    tile_compute<4>(aAH[0], aAL[0], aBH[0], aBL[0], wm, wn, lane, c);
    CPA_WAIT0();
    __syncthreads();
    tile_compute<4>(aAH[1], aAL[1], aBH[1], aBL[1], wm, wn, lane, c);
    __syncthreads();

    float2* spair = (float2*)sm;
    const int g = lane >> 2, tg = lane & 3;

#pragma unroll
    for (int mi = 0; mi < 4; mi++)
#pragma unroll
        for (int half = 0; half < 2; half++) {
            const int rloc = wm*64 + mi*16 + half*8 + g;
            const int t = m0 + rloc;
            const float mt = 1.0f - pad[b*SS + t];
            const float* bp = &bias4d[((size_t)bh*SS + t)*SS + n0];
            float* ap = &attn[((size_t)bh*SS + t)*SS + n0];
            float vv[8];
#pragma unroll
            for (int ni = 0; ni < 4; ni++) {
                const int nl = wn*32 + ni*8 + tg*2;
                const float ms0 = 1.0f - pad[b*SS + n0 + nl];
                const float ms1 = 1.0f - pad[b*SS + n0 + nl + 1];
                float x0 = c[mi][ni][half*2+0]*0.125f + bp[nl]   - 1e9f*(1.0f - mt*ms0);
                float x1 = c[mi][ni][half*2+1]*0.125f + bp[nl+1] - 1e9f*(1.0f - mt*ms1);
                vv[ni*2]   = x0;
                vv[ni*2+1] = x1;
                float2 w = { x0, x1 };
                *(float2*)&ap[nl] = w;
            }
            float mx = vv[0];
#pragma unroll
            for (int j = 1; j < 8; j++) mx = fmaxf(mx, vv[j]);
            mx = fmaxf(mx, __shfl_xor_sync(~0u, mx, 1));
            mx = fmaxf(mx, __shfl_xor_sync(~0u, mx, 2));
            float se = 0.f;
#pragma unroll
            for (int j = 0; j < 8; j++) se += __expf(vv[j] - mx);
            se += __shfl_xor_sync(~0u, se, 1);
            se += __shfl_xor_sync(~0u, se, 2);
            if (tg == 0) spair[wn*128 + rloc] = make_float2(mx, se);
        }
    __syncthreads();

    if (tid < 128) {
        float2 p0 = spair[tid], p1 = spair[128 + tid];
        float2 p2 = spair[256 + tid], p3 = spair[384 + tid];
        float m01 = fmaxf(p0.x, p1.x), m23 = fmaxf(p2.x, p3.x);
        float m = fmaxf(m01, m23);
        float s = p0.y*__expf(p0.x - m) + p1.y*__expf(p1.x - m)
                + p2.y*__expf(p2.x - m) + p3.y*__expf(p3.x - m);
        part[(((size_t)bh*SS) + m0 + tid)*16 + stile] = make_float2(m, s);
    }
}

// ---- merge 16 partials per row -> (max, 1/sum) ----
__global__ void ms_reduce_kernel(const float2* __restrict__ part,
                                 float2* __restrict__ ms)
{
    const int row = blockIdx.x * 256 + threadIdx.x;
    const float2* p = part + (size_t)row * 16;
    float2 v[16];
#pragma unroll
    for (int i = 0; i < 8; i++) {
        float4 a = *(const float4*)&p[i*2];
        v[i*2]   = make_float2(a.x, a.y);
        v[i*2+1] = make_float2(a.z, a.w);
    }
    float m = v[0].x;
#pragma unroll
    for (int i = 1; i < 16; i++) m = fmaxf(m, v[i].x);
    float s = 0.f;
#pragma unroll
    for (int i = 0; i < 16; i++) s += v[i].y * __expf(v[i].x - m);
    ms[row] = make_float2(m, 1.0f / s);
}

// ===========================================================================
// AV fused: normalize + write weights + split + MMA. grid (16,32). dyn 78848.
// ===========================================================================
__global__ __launch_bounds__(256) void av_pipe_kernel(
    float* __restrict__ attn,
    const float2* __restrict__ ms,
    const __nv_bfloat16* __restrict__ VTh, const __nv_bfloat16* __restrict__ VTl,
    __nv_bfloat16* __restrict__ Ch, __nv_bfloat16* __restrict__ Cl)
{
    extern __shared__ char sm[];
    const uint32_t sb = s2u(sm);
    const uint32_t aAF[2] = { sb, sb + 18432 };
    const uint32_t aAH = sb + 36864, aAL = sb + 47104;
    const uint32_t aBH[2] = { sb + 57344, sb + 62464 };
    const uint32_t aBL[2] = { sb + 67584, sb + 72704 };
    float2* sms = (float2*)(sm + 77824);

    const int tid = threadIdx.x, lane = tid & 31, wid = tid >> 5;
    const int wm = wid >> 2, wn = wid & 3;
    const int bh = blockIdx.y, b = bh >> 4, hd = bh & 15;
    const int m0 = blockIdx.x * 128;

    float* Abf = attn + ((size_t)bh*SS + m0) * SS;
    const __nv_bfloat16* Bbh = VTh + (size_t)bh*DD*SS;
    const __nv_bfloat16* Bbl = VTl + (size_t)bh*DD*SS;

    if (tid < 128) sms[tid] = ms[(size_t)bh*SS + m0 + tid];

    float c[4][2][4] = {};

    auto load_stage = [&](int st, int k0){
        for (int idx = tid; idx < 1024; idx += 256) {
            int r = idx >> 3, cc = idx & 7;
            cpa16(aAF[st] + (uint32_t)r*144 + cc*16, Abf + (size_t)r*SS + k0 + cc*4);
        }
        for (int idx = tid; idx < 256; idx += 256) {
            int r = idx >> 2, cc = idx & 3;
            uint32_t so = (uint32_t)r*80 + cc*16;
            size_t go = (size_t)r*SS + k0 + cc*8;
            cpa16(aBH[st] + so, Bbh + go);
            cpa16(aBL[st] + so, Bbl + go);
        }
    };

    load_stage(0, 0);  CPA_COMMIT();
    load_stage(1, 32); CPA_COMMIT();

    for (int kt = 0; kt < 64; kt++) {
        if (kt + 1 < 64) { CPA_WAIT1(); } else { CPA_WAIT0(); }
        __syncthreads();
        const int st = kt & 1;
        const int k0 = kt * 32;
        for (int idx = tid; idx < 1024; idx += 256) {
            int r = idx >> 3, cc = idx & 7;
            float4 w = *(const float4*)(sm + st*18432 + r*144 + cc*16);
            float2 q = sms[r];
            w.x = __expf(w.x - q.x) * q.y;
            w.y = __expf(w.y - q.x) * q.y;
            w.z = __expf(w.z - q.x) * q.y;
            w.w = __expf(w.w - q.x) * q.y;
            *(float4*)&Abf[(size_t)r*SS + k0 + cc*4] = w;
            __nv_bfloat16 h0,h1,h2,h3,l0,l1,l2,l3;
            bsplit(w.x,h0,l0); bsplit(w.y,h1,l1); bsplit(w.z,h2,l2); bsplit(w.w,h3,l3);
            uint2 hp = { pk2(h0,h1), pk2(h2,h3) };
            uint2 lp = { pk2(l0,l1), pk2(l2,l3) };
            *(uint2*)(sm + 36864 + r*80 + cc*8) = hp;
            *(uint2*)(sm + 47104 + r*80 + cc*8) = lp;
        }
        __syncthreads();
        tile_compute<2>(aAH, aAL, aBH[st], aBL[st], wm, wn, lane, c);
        __syncthreads();
        if (kt + 2 < 64) { load_stage(st, (kt + 2) * 32); CPA_COMMIT(); }
    }

    const int g = lane >> 2, tg = lane & 3;
#pragma unroll
    for (int mi = 0; mi < 4; mi++)
#pragma unroll
        for (int ni = 0; ni < 2; ni++) {
            const int m = m0 + wm*64 + mi*16 + g;
            const int n = wn*16 + ni*8 + tg*2;
            const size_t base = ((size_t)(b*SS + m))*DIM + hd*DD + n;
            __nv_bfloat16 h0,h1,h2,h3,l0,l1,l2,l3;
            bsplit(c[mi][ni][0], h0, l0); bsplit(c[mi][ni][1], h1, l1);
            bsplit(c[mi][ni][2], h2, l2); bsplit(c[mi][ni][3], h3, l3);
            *(uint32_t*)&Ch[base]         = pk2(h0, h1);
            *(uint32_t*)&Cl[base]         = pk2(l0, l1);
            *(uint32_t*)&Ch[base + 8*DIM] = pk2(h2, h3);
            *(uint32_t*)&Cl[base + 8*DIM] = pk2(l2, l3);
        }
}

// ---------------------------------------------------------------------------
extern "C" void kernel_launch(void* const* d_in, const int* in_sizes, int n_in,
                              void* d_out, int out_size)
{
    const float* attnbias = (const float*)d_in[3];
    const float* paddings = (const float*)d_in[4];
    const float* ww[4] = { (const float*)d_in[5], (const float*)d_in[7],
                           (const float*)d_in[9], (const float*)d_in[11] };
    const float* wb[4] = { (const float*)d_in[6], (const float*)d_in[8],
                           (const float*)d_in[10], (const float*)d_in[12] };

    float* out  = (float*)d_out;
    float* attn = out + (size_t)MT * DIM;

    __nv_bfloat16 *twh, *twl, *ph, *pl, *vth, *vtl, *ch, *cl;
    float2 *partp, *msp;
    cudaGetSymbolAddress((void**)&twh, g_twh); cudaGetSymbolAddress((void**)&twl, g_twl);
    cudaGetSymbolAddress((void**)&ph, g_ph);   cudaGetSymbolAddress((void**)&pl, g_pl);
    cudaGetSymbolAddress((void**)&vth, g_vth); cudaGetSymbolAddress((void**)&vtl, g_vtl);
    cudaGetSymbolAddress((void**)&ch, g_ch);   cudaGetSymbolAddress((void**)&cl, g_cl);
    cudaGetSymbolAddress((void**)&partp, g_part); cudaGetSymbolAddress((void**)&msp, g_ms);

    static int attr_done = 0;
    if (!attr_done) {
        cudaFuncSetAttribute(qkv_pipe_kernel,      cudaFuncAttributeMaxDynamicSharedMemorySize, Q_SMEM);
        cudaFuncSetAttribute(gemm_pipe_kernel,     cudaFuncAttributeMaxDynamicSharedMemorySize, 81920);
        cudaFuncSetAttribute(logits_fused_kernel,  cudaFuncAttributeMaxDynamicSharedMemorySize, 81920);
        cudaFuncSetAttribute(av_pipe_kernel,       cudaFuncAttributeMaxDynamicSharedMemorySize, 78848);
        attr_done = 1;
    }

    const size_t NX = (size_t)MT * DIM;
    const size_t NW = (size_t)DIM * DIM;

    for (int i = 0; i < 4; i++)
        wtrans_kernel<<<dim3(32,32), dim3(32,8)>>>(ww[i], twh + i*NW, twl + i*NW);

    // QKV projections with fused input split
    qkv_pipe_kernel<<<dim3(8,32,3), 256, Q_SMEM>>>(
        (const float*)d_in[0], (const float*)d_in[1], (const float*)d_in[2],
        twh, twl, wb[0], wb[1], wb[2], ph, pl);

    __nv_bfloat16 *qh = ph, *ql = pl;
    __nv_bfloat16 *kh = ph + NX, *kl = pl + NX;
    __nv_bfloat16 *vh = ph + 2*NX, *vl = pl + 2*NX;

    // V transpose, hi+lo in one launch
    vtrans_kernel<<<dim3(32, NBH, 2), 256>>>(vh, vl, vth, vtl);

    // logits + bias + mask + softmax partials
    logits_fused_kernel<<<dim3(16,16,NBH), 256, 81920>>>(
        qh, ql, kh, kl, attnbias, paddings, attn, partp);

    // merge partials -> (max, 1/sum) per row
    ms_reduce_kernel<<<(NBH*SS)/256, 256>>>(partp, msp);

    // AV: normalize + write weights + MMA
    av_pipe_kernel<<<dim3(16, NBH), 256, 78848>>>(attn, msp, vth, vtl, ch, cl);

    // output projection -> fp32 out
    gemm_pipe_kernel<<<dim3(8,32), 256, 81920>>>(
        ch, cl, twh + 3*NW, twl + 3*NW, wb[3], out);
}